// round 9
// baseline (speedup 1.0000x reference)
#include <cuda_runtime.h>
#include <cstdint>

#define V      50000
#define BATCH  64
#define MLEN   2048
#define DIM    128
#define NPART  148
#define NSTEPS 3125   // V/16 exactly
#define NTOK   (MLEN * BATCH * 4)   // 524288 tokens

// ---------------- scratch (device globals; no allocs allowed) ----------------
__device__ float g_w[3 * V * BATCH];          // wT[hop][v][b]  (38.4 MB)
__device__ float g_proj[V * BATCH];           // proj[v][b]     (12.8 MB)
__device__ float g_prob[BATCH * MLEN];        // scores -> probs [b][m]
__device__ float g_u[BATCH * DIM];            // running u [b][d]
__device__ float g_part[NPART * BATCH * DIM]; // split-K partials (4.85 MB)
__device__ int   g_tok[NTOK];                 // normalized int32 tokens (2 MB)
__device__ int   g_is32;                      // dtype probe result

// ---------------- f32x2 helpers (FFMA2 — only reachable via PTX) -------------
__device__ __forceinline__ unsigned long long pk2(float lo, float hi) {
    unsigned long long r;
    asm("mov.b64 %0, {%1, %2};" : "=l"(r) : "f"(lo), "f"(hi));
    return r;
}
__device__ __forceinline__ void fma2(unsigned long long& d,
                                     unsigned long long a,
                                     unsigned long long b) {
    asm("fma.rn.f32x2 %0, %1, %2, %0;" : "+l"(d) : "l"(a), "l"(b));
}
__device__ __forceinline__ float2 upk(unsigned long long v) {
    float2 f;
    asm("mov.b64 {%0, %1}, %2;" : "=f"(f.x), "=f"(f.y) : "l"(v));
    return f;
}

// ---------------- K0: zero accumulators (every replay) -----------------------
__global__ void k_zero() {
    const float4 z = make_float4(0.f, 0.f, 0.f, 0.f);
    int t = blockIdx.x * blockDim.x + threadIdx.x;
    int stride = gridDim.x * blockDim.x;
    float4* w4 = reinterpret_cast<float4*>(g_w);
    const int NW4 = 3 * V * BATCH / 4;  // 2,400,000
    for (int i = t; i < NW4; i += stride) w4[i] = z;
    if (t < (BATCH * DIM / 4)) reinterpret_cast<float4*>(g_u)[t] = z;
    if (t == 0) g_is32 = 0;
}

// ---------------- K0b: dtype probe -------------------------------------------
__global__ void k_detect(const unsigned* __restrict__ s) {
    int t = blockIdx.x * blockDim.x + threadIdx.x;
    int stride = gridDim.x * blockDim.x;
    int found = 0;
    for (int w = 2 * t + 1; w < NTOK; w += 2 * stride)
        found |= (s[w] != 0u);
    if (found) g_is32 = 1;
}

// ---------------- K0c: normalize story into g_tok ----------------------------
__global__ void k_convert(const int* __restrict__ s) {
    int t = blockIdx.x * blockDim.x + threadIdx.x;
    if (t >= NTOK) return;
    g_tok[t] = g_is32 ? s[t] : s[2 * t];   // int64: low word at 2*t (LE)
}

// ---------------- K1: scatter counts for hop0 (1 thread / token) -------------
__global__ void k_scatter_count() {
    int t = blockIdx.x * blockDim.x + threadIdx.x;
    if (t >= NTOK) return;
    int b = (t >> 2) & (BATCH - 1);
    int tok = g_tok[t];
    if (tok) atomicAdd(&g_w[tok * BATCH + b], 1.0f);
}

// ---------------- K2: proj[v][b] = C[h][v] . u[b]  (V x 64, K=128) -----------
#define AS_W 132
#define BS_W 68
__global__ __launch_bounds__(256) void k_proj(const float* __restrict__ Ct) {
    __shared__ __align__(16) float As[16 * AS_W];
    __shared__ __align__(16) float Bs[16 * BS_W];
    int t = threadIdx.x;
    int v0 = blockIdx.x * 128;
    int vg = t & 15;
    int bg = t >> 4;
    unsigned long long acc[4][4];
#pragma unroll
    for (int i = 0; i < 4; i++)
#pragma unroll
        for (int j = 0; j < 4; j++) acc[i][j] = 0ULL;

    float rc[8], rb[4];
    // prefetch kk = 0
#pragma unroll
    for (int i = 0; i < 8; i++) {
        int e = t + i * 256;
        int k = e & 15, v = e >> 4;
        int gv = v0 + v;
        rc[i] = (gv < V) ? Ct[(size_t)gv * DIM + k] : 0.f;
    }
#pragma unroll
    for (int i = 0; i < 4; i++) {
        int e = t + i * 256;
        int k = e & 15, b = e >> 4;
        rb[i] = g_u[b * DIM + k];
    }

#pragma unroll 1
    for (int kk = 0; kk < 8; kk++) {
#pragma unroll
        for (int i = 0; i < 8; i++) {
            int e = t + i * 256;
            As[(e & 15) * AS_W + (e >> 4)] = rc[i];
        }
#pragma unroll
        for (int i = 0; i < 4; i++) {
            int e = t + i * 256;
            Bs[(e & 15) * BS_W + (e >> 4)] = rb[i];
        }
        __syncthreads();
        if (kk < 7) {                      // prefetch kk+1 (hidden by compute)
            int kb = (kk + 1) * 16;
#pragma unroll
            for (int i = 0; i < 8; i++) {
                int e = t + i * 256;
                int k = e & 15, v = e >> 4;
                int gv = v0 + v;
                rc[i] = (gv < V) ? Ct[(size_t)gv * DIM + kb + k] : 0.f;
            }
#pragma unroll
            for (int i = 0; i < 4; i++) {
                int e = t + i * 256;
                int k = e & 15, b = e >> 4;
                rb[i] = g_u[b * DIM + kb + k];
            }
        }
#pragma unroll
        for (int k = 0; k < 16; k++) {
            const ulonglong2* ap =
                reinterpret_cast<const ulonglong2*>(&As[k * AS_W + vg * 8]);
            ulonglong2 a01 = ap[0], a23 = ap[1];
            float4 b4 = *reinterpret_cast<const float4*>(&Bs[k * BS_W + bg * 4]);
            unsigned long long bd0 = pk2(b4.x, b4.x), bd1 = pk2(b4.y, b4.y);
            unsigned long long bd2 = pk2(b4.z, b4.z), bd3 = pk2(b4.w, b4.w);
            fma2(acc[0][0], a01.x, bd0); fma2(acc[0][1], a01.x, bd1);
            fma2(acc[0][2], a01.x, bd2); fma2(acc[0][3], a01.x, bd3);
            fma2(acc[1][0], a01.y, bd0); fma2(acc[1][1], a01.y, bd1);
            fma2(acc[1][2], a01.y, bd2); fma2(acc[1][3], a01.y, bd3);
            fma2(acc[2][0], a23.x, bd0); fma2(acc[2][1], a23.x, bd1);
            fma2(acc[2][2], a23.x, bd2); fma2(acc[2][3], a23.x, bd3);
            fma2(acc[3][0], a23.y, bd0); fma2(acc[3][1], a23.y, bd1);
            fma2(acc[3][2], a23.y, bd2); fma2(acc[3][3], a23.y, bd3);
        }
        __syncthreads();
    }
#pragma unroll
    for (int ip = 0; ip < 4; ip++) {
        float2 r0 = upk(acc[ip][0]), r1 = upk(acc[ip][1]);
        float2 r2 = upk(acc[ip][2]), r3 = upk(acc[ip][3]);
        int ve = v0 + vg * 8 + ip * 2;
        if (ve < V)
            *reinterpret_cast<float4*>(&g_proj[(size_t)ve * BATCH + bg * 4]) =
                make_float4(r0.x, r1.x, r2.x, r3.x);
        if (ve + 1 < V)
            *reinterpret_cast<float4*>(&g_proj[(size_t)(ve + 1) * BATCH + bg * 4]) =
                make_float4(r0.y, r1.y, r2.y, r3.y);
    }
}

// ---------------- K3: scores, 1 thread/token + 4-lane shfl reduce ------------
__global__ void k_scores() {
    int t = blockIdx.x * blockDim.x + threadIdx.x;
    if (t >= NTOK) return;
    int j = t & 3;
    int b = (t >> 2) & (BATCH - 1);
    int m = t >> 8;
    int tok = g_tok[t];
    float v = tok ? __ldg(&g_proj[(size_t)tok * BATCH + b]) : 0.f;
    v += __shfl_down_sync(0xffffffffu, v, 2);
    v += __shfl_down_sync(0xffffffffu, v, 1);
    if (j == 0) g_prob[b * MLEN + m] = v;
}

// ---------------- K4: softmax over M per batch -------------------------------
__global__ void k_softmax() {
    __shared__ __align__(16) float sc[MLEN];
    __shared__ float red[256];
    int b = blockIdx.x, t = threadIdx.x;
    float lmax = -1e30f;
#pragma unroll
    for (int i = 0; i < 8; i++) {
        float v = g_prob[b * MLEN + t + i * 256];
        sc[t + i * 256] = v;
        lmax = fmaxf(lmax, v);
    }
    red[t] = lmax; __syncthreads();
    for (int s = 128; s > 0; s >>= 1) {
        if (t < s) red[t] = fmaxf(red[t], red[t + s]);
        __syncthreads();
    }
    float mx = red[0]; __syncthreads();
    float lsum = 0.f;
#pragma unroll
    for (int i = 0; i < 8; i++) {
        float e = expf(sc[t + i * 256] - mx);
        sc[t + i * 256] = e;
        lsum += e;
    }
    red[t] = lsum; __syncthreads();
    for (int s = 128; s > 0; s >>= 1) {
        if (t < s) red[t] += red[t + s];
        __syncthreads();
    }
    float inv = 1.0f / red[0];
#pragma unroll
    for (int i = 0; i < 8; i++)
        g_prob[b * MLEN + t + i * 256] = sc[t + i * 256] * inv;
}

// ---------------- K5: scatter probs into wT[hop] (1 thread / token) ----------
__global__ void k_scatter_prob(int hop) {
    int t = blockIdx.x * blockDim.x + threadIdx.x;
    if (t >= NTOK) return;
    int b = (t >> 2) & (BATCH - 1);
    int m = t >> 8;
    int tok = g_tok[t];
    if (tok) {
        float p = g_prob[b * MLEN + m];
        atomicAdd(&g_w[(size_t)hop * V * BATCH + tok * BATCH + b], p);
    }
}

// ---------------- K6: o[b][d] partials = w @ C[tab]  (split-K, prefetched) ---
__global__ __launch_bounds__(256) void k_gemm2(const float* __restrict__ Ct,
                                               int hop) {
    __shared__ __align__(16) float Cs[16 * 128];
    __shared__ __align__(16) float Ws[16 * 64];
    const float* wT = g_w + (size_t)hop * V * BATCH;
    int t = threadIdx.x;
    int dg = t & 31;
    int bgp = t >> 5;
    int s0 = (int)((long long)blockIdx.x * NSTEPS / NPART);
    int s1 = (int)((long long)(blockIdx.x + 1) * NSTEPS / NPART);
    unsigned long long acc[4][4];
#pragma unroll
    for (int i = 0; i < 4; i++)
#pragma unroll
        for (int j = 0; j < 4; j++) acc[i][j] = 0ULL;

    float rc[8], rw[4];
    {   // prefetch s0
        int vb = s0 * 16;
#pragma unroll
        for (int i = 0; i < 8; i++) rc[i] = Ct[(size_t)vb * 128 + t + i * 256];
#pragma unroll
        for (int i = 0; i < 4; i++) rw[i] = wT[(size_t)vb * 64 + t + i * 256];
    }

    for (int s = s0; s < s1; s++) {
#pragma unroll
        for (int i = 0; i < 8; i++) Cs[t + i * 256] = rc[i];
#pragma unroll
        for (int i = 0; i < 4; i++) Ws[t + i * 256] = rw[i];
        __syncthreads();
        if (s + 1 < s1) {                  // prefetch s+1 (hidden by compute)
            int vb = (s + 1) * 16;
#pragma unroll
            for (int i = 0; i < 8; i++) rc[i] = Ct[(size_t)vb * 128 + t + i * 256];
#pragma unroll
            for (int i = 0; i < 4; i++) rw[i] = wT[(size_t)vb * 64 + t + i * 256];
        }
#pragma unroll
        for (int vv = 0; vv < 16; vv++) {
            const ulonglong2* wp =
                reinterpret_cast<const ulonglong2*>(&Ws[vv * 64 + bgp * 8]);
            ulonglong2 w01 = wp[0], w23 = wp[1];
            float4 c4 = *reinterpret_cast<const float4*>(&Cs[vv * 128 + dg * 4]);
            unsigned long long cd0 = pk2(c4.x, c4.x), cd1 = pk2(c4.y, c4.y);
            unsigned long long cd2 = pk2(c4.z, c4.z), cd3 = pk2(c4.w, c4.w);
            fma2(acc[0][0], w01.x, cd0); fma2(acc[0][1], w01.x, cd1);
            fma2(acc[0][2], w01.x, cd2); fma2(acc[0][3], w01.x, cd3);
            fma2(acc[1][0], w01.y, cd0); fma2(acc[1][1], w01.y, cd1);
            fma2(acc[1][2], w01.y, cd2); fma2(acc[1][3], w01.y, cd3);
            fma2(acc[2][0], w23.x, cd0); fma2(acc[2][1], w23.x, cd1);
            fma2(acc[2][2], w23.x, cd2); fma2(acc[2][3], w23.x, cd3);
            fma2(acc[3][0], w23.y, cd0); fma2(acc[3][1], w23.y, cd1);
            fma2(acc[3][2], w23.y, cd2); fma2(acc[3][3], w23.y, cd3);
        }
        __syncthreads();
    }
    float* pp = g_part + (size_t)blockIdx.x * (BATCH * DIM);
#pragma unroll
    for (int bp = 0; bp < 4; bp++) {
        float2 e0 = upk(acc[bp][0]), e1 = upk(acc[bp][1]);
        float2 e2 = upk(acc[bp][2]), e3 = upk(acc[bp][3]);
        int be = bgp * 8 + bp * 2;
        *reinterpret_cast<float4*>(&pp[be * DIM + dg * 4]) =
            make_float4(e0.x, e1.x, e2.x, e3.x);
        *reinterpret_cast<float4*>(&pp[(be + 1) * DIM + dg * 4]) =
            make_float4(e0.y, e1.y, e2.y, e3.y);
    }
}

// ---------------- K7: reduce partials, update u, optionally emit out ---------
__global__ void k_reduce(float scale, float* out) {
    int i = blockIdx.x * blockDim.x + threadIdx.x;   // 8192
    float s = 0.f;
    int k = 0;
#pragma unroll
    for (; k + 8 <= NPART; k += 8) {
        float a0 = g_part[(size_t)(k + 0) * (BATCH * DIM) + i];
        float a1 = g_part[(size_t)(k + 1) * (BATCH * DIM) + i];
        float a2 = g_part[(size_t)(k + 2) * (BATCH * DIM) + i];
        float a3 = g_part[(size_t)(k + 3) * (BATCH * DIM) + i];
        float a4 = g_part[(size_t)(k + 4) * (BATCH * DIM) + i];
        float a5 = g_part[(size_t)(k + 5) * (BATCH * DIM) + i];
        float a6 = g_part[(size_t)(k + 6) * (BATCH * DIM) + i];
        float a7 = g_part[(size_t)(k + 7) * (BATCH * DIM) + i];
        s += ((a0 + a1) + (a2 + a3)) + ((a4 + a5) + (a6 + a7));
    }
    for (; k < NPART; k++) s += g_part[(size_t)k * (BATCH * DIM) + i];
    float un = g_u[i] + scale * s;
    g_u[i] = un;
    if (out) out[i] = un;
}

// -----------------------------------------------------------------------------
extern "C" void kernel_launch(void* const* d_in, const int* in_sizes, int n_in,
                              void* d_out, int out_size) {
    const void* story;
    const float* C;
    if (in_sizes[0] == NTOK) {
        story = d_in[0];
        C = (const float*)d_in[1];
    } else {
        story = d_in[1];
        C = (const float*)d_in[0];
    }
    float* out = (float*)d_out;
    const float* C1 = C + (size_t)1 * V * DIM;
    const float* C2 = C + (size_t)2 * V * DIM;
    const float* C3 = C + (size_t)3 * V * DIM;

    const int PROJ_BLKS = (V + 127) / 128;   // 391
    const int TOK_BLKS = NTOK / 256;         // 2048

    k_zero<<<2048, 256>>>();
    k_detect<<<256, 256>>>((const unsigned*)story);
    k_convert<<<TOK_BLKS, 256>>>((const int*)story);

    // hop 0: uniform softmax -> u1 = (1/M) * counts @ C1
    k_scatter_count<<<TOK_BLKS, 256>>>();
    k_gemm2<<<NPART, 256>>>(C1, 0);
    k_reduce<<<32, 256>>>(1.0f / (float)MLEN, nullptr);

    // hop 1: scores with C1 & u1, values from C2
    k_proj<<<PROJ_BLKS, 256>>>(C1);
    k_scores<<<TOK_BLKS, 256>>>();
    k_softmax<<<BATCH, 256>>>();
    k_scatter_prob<<<TOK_BLKS, 256>>>(1);
    k_gemm2<<<NPART, 256>>>(C2, 1);
    k_reduce<<<32, 256>>>(1.0f, nullptr);

    // hop 2: scores with C2 & u2, values from C3
    k_proj<<<PROJ_BLKS, 256>>>(C2);
    k_scores<<<TOK_BLKS, 256>>>();
    k_softmax<<<BATCH, 256>>>();
    k_scatter_prob<<<TOK_BLKS, 256>>>(2);
    k_gemm2<<<NPART, 256>>>(C3, 2);
    k_reduce<<<32, 256>>>(1.0f, out);
}

// round 11
// speedup vs baseline: 1.4598x; 1.4598x over previous
#include <cuda_runtime.h>
#include <cuda_bf16.h>
#include <cstdint>

#define V      50000
#define BATCH  64
#define MLEN   2048
#define DIM    128
#define NPART  148
#define NSTEPS 3125   // V/16 exactly
#define NTOK   (MLEN * BATCH * 4)   // 524288 tokens

// ---------------- scratch (device globals; no allocs allowed) ----------------
__device__ float g_w[V * BATCH];              // w[b][v] (12.8 MB, L2-hot)
__device__ float g_proj[V * BATCH];           // proj[v][b] (12.8 MB)
__device__ float g_prob[BATCH * MLEN];        // probs [b][m]
__device__ float g_u[BATCH * DIM];            // running u [b][d]
__device__ float g_part[NPART * BATCH * DIM]; // split-K partials (4.85 MB)
__device__ int   g_tok[NTOK];                 // normalized int32 tokens (2 MB)
__device__ int   g_is32;

// ---------------- mma.sync bf16 (sm_80+ PTX, works on sm_103 base) -----------
__device__ __forceinline__ void mma_bf16(float* d, uint32_t a0, uint32_t a1,
                                         uint32_t a2, uint32_t a3,
                                         uint32_t b0, uint32_t b1) {
    asm volatile(
        "mma.sync.aligned.m16n8k16.row.col.f32.bf16.bf16.f32 "
        "{%0,%1,%2,%3}, {%4,%5,%6,%7}, {%8,%9}, {%0,%1,%2,%3};"
        : "+f"(d[0]), "+f"(d[1]), "+f"(d[2]), "+f"(d[3])
        : "r"(a0), "r"(a1), "r"(a2), "r"(a3), "r"(b0), "r"(b1));
}
// split fp32 -> (bf16 hi, bf16 lo)
__device__ __forceinline__ void split2(float x, float y, uint32_t& hi,
                                       uint32_t& lo) {
    __nv_bfloat16 hx = __float2bfloat16(x), hy = __float2bfloat16(y);
    __nv_bfloat162 H = __halves2bfloat162(hx, hy);
    __nv_bfloat162 L = __halves2bfloat162(
        __float2bfloat16(x - __bfloat162float(hx)),
        __float2bfloat16(y - __bfloat162float(hy)));
    hi = *reinterpret_cast<uint32_t*>(&H);
    lo = *reinterpret_cast<uint32_t*>(&L);
}

// ---------------- K0: zero w + u + flag --------------------------------------
__global__ void k_zero() {
    const float4 z = make_float4(0.f, 0.f, 0.f, 0.f);
    int t = blockIdx.x * blockDim.x + threadIdx.x;
    int stride = gridDim.x * blockDim.x;
    float4* w4 = reinterpret_cast<float4*>(g_w);
    for (int i = t; i < V * BATCH / 4; i += stride) w4[i] = z;
    if (t < (BATCH * DIM / 4)) reinterpret_cast<float4*>(g_u)[t] = z;
    if (t == 0) g_is32 = 0;
}

// ---------------- K0b: dtype probe -------------------------------------------
__global__ void k_detect(const unsigned* __restrict__ s) {
    int t = blockIdx.x * blockDim.x + threadIdx.x;   // 4096 threads
    if (s[2 * t + 1] != 0u) g_is32 = 1;
}

// ---------------- K0c: convert story + scatter hop0 counts (fused) -----------
__global__ void k_prep(const int* __restrict__ s) {
    int t = blockIdx.x * blockDim.x + threadIdx.x;
    if (t >= NTOK) return;
    int tok = g_is32 ? s[t] : s[2 * t];   // int64 LE: low word at 2*t
    g_tok[t] = tok;
    if (tok) {
        int b = (t >> 2) & (BATCH - 1);
        atomicAdd(&g_w[b * V + tok], 1.0f);
    }
}

// ---------------- K2: proj[v][b] = C[v][:] . u[b][:] via mma.sync ------------
// CTA: 128 v-rows x 64 b. Both operands k-contiguous -> direct fragment LDS.
#define PPS 136                       // padded k-stride (bf16 units)
#define A_HI_OFF 0
#define A_LO_OFF 34816                // 128*136*2
#define B_HI_OFF 69632
#define B_LO_OFF 87040                // +64*136*2
#define PROJ_SMEM 104448

__global__ __launch_bounds__(256) void k_proj_mma(const float* __restrict__ Ct) {
    extern __shared__ __align__(16) char sm[];
    int tid = threadIdx.x;
    int wid = tid >> 5, lane = tid & 31;
    int g = lane >> 2, tig = lane & 3;
    int v0 = blockIdx.x * 128;

    // stage A = C[v0..v0+128][0..128] as bf16 hi/lo (k-pairs)
#pragma unroll
    for (int i = 0; i < 32; i++) {
        int p = tid + i * 256;            // pair index, 8192 pairs
        int row = p >> 6, kp = p & 63;
        int gv = v0 + row;
        float2 c = make_float2(0.f, 0.f);
        if (gv < V)
            c = *reinterpret_cast<const float2*>(Ct + (size_t)gv * DIM + 2 * kp);
        uint32_t hi, lo;
        split2(c.x, c.y, hi, lo);
        int off = 4 * (row * (PPS / 2) + kp);
        *reinterpret_cast<uint32_t*>(sm + A_HI_OFF + off) = hi;
        *reinterpret_cast<uint32_t*>(sm + A_LO_OFF + off) = lo;
    }
    // stage B = u[0..64][0..128]
#pragma unroll
    for (int i = 0; i < 16; i++) {
        int p = tid + i * 256;            // 4096 pairs
        int row = p >> 6, kp = p & 63;
        float2 c = *reinterpret_cast<const float2*>(g_u + row * DIM + 2 * kp);
        uint32_t hi, lo;
        split2(c.x, c.y, hi, lo);
        int off = 4 * (row * (PPS / 2) + kp);
        *reinterpret_cast<uint32_t*>(sm + B_HI_OFF + off) = hi;
        *reinterpret_cast<uint32_t*>(sm + B_LO_OFF + off) = lo;
    }
    __syncthreads();

    float acc[8][4];
#pragma unroll
    for (int i = 0; i < 8; i++)
#pragma unroll
        for (int j = 0; j < 4; j++) acc[i][j] = 0.f;

    int arow = wid * 16 + g;
#pragma unroll
    for (int ks = 0; ks < 8; ks++) {
        int kb = ks * 16;
        int ao = kb + 2 * tig;
        uint32_t ah0 = *reinterpret_cast<uint32_t*>(sm + A_HI_OFF + 2 * (arow * PPS + ao));
        uint32_t ah1 = *reinterpret_cast<uint32_t*>(sm + A_HI_OFF + 2 * ((arow + 8) * PPS + ao));
        uint32_t ah2 = *reinterpret_cast<uint32_t*>(sm + A_HI_OFF + 2 * (arow * PPS + ao + 8));
        uint32_t ah3 = *reinterpret_cast<uint32_t*>(sm + A_HI_OFF + 2 * ((arow + 8) * PPS + ao + 8));
        uint32_t al0 = *reinterpret_cast<uint32_t*>(sm + A_LO_OFF + 2 * (arow * PPS + ao));
        uint32_t al1 = *reinterpret_cast<uint32_t*>(sm + A_LO_OFF + 2 * ((arow + 8) * PPS + ao));
        uint32_t al2 = *reinterpret_cast<uint32_t*>(sm + A_LO_OFF + 2 * (arow * PPS + ao + 8));
        uint32_t al3 = *reinterpret_cast<uint32_t*>(sm + A_LO_OFF + 2 * ((arow + 8) * PPS + ao + 8));
#pragma unroll
        for (int nt = 0; nt < 8; nt++) {
            int bcol = nt * 8 + g;
            uint32_t bh0 = *reinterpret_cast<uint32_t*>(sm + B_HI_OFF + 2 * (bcol * PPS + ao));
            uint32_t bh1 = *reinterpret_cast<uint32_t*>(sm + B_HI_OFF + 2 * (bcol * PPS + ao + 8));
            uint32_t bl0 = *reinterpret_cast<uint32_t*>(sm + B_LO_OFF + 2 * (bcol * PPS + ao));
            uint32_t bl1 = *reinterpret_cast<uint32_t*>(sm + B_LO_OFF + 2 * (bcol * PPS + ao + 8));
            mma_bf16(acc[nt], ah0, ah1, ah2, ah3, bh0, bh1);
            mma_bf16(acc[nt], ah0, ah1, ah2, ah3, bl0, bl1);
            mma_bf16(acc[nt], al0, al1, al2, al3, bh0, bh1);
        }
    }
    // write proj: c0,c1 -> (row g, cols 2tig..), c2,c3 -> row g+8
    int vA = v0 + arow, vB = vA + 8;
#pragma unroll
    for (int nt = 0; nt < 8; nt++) {
        int col = nt * 8 + 2 * tig;
        if (vA < V)
            *reinterpret_cast<float2*>(&g_proj[(size_t)vA * BATCH + col]) =
                make_float2(acc[nt][0], acc[nt][1]);
        if (vB < V)
            *reinterpret_cast<float2*>(&g_proj[(size_t)vB * BATCH + col]) =
                make_float2(acc[nt][2], acc[nt][3]);
    }
}

// ---------------- K3: scores + softmax fused (block = one batch b) -----------
__global__ void k_scores_smax() {
    __shared__ __align__(16) float sc[MLEN];
    __shared__ float red[256];
    int b = blockIdx.x, t = threadIdx.x;
    float lmax = -1e30f;
#pragma unroll
    for (int i = 0; i < 8; i++) {
        int m = i * 256 + t;
        int4 s4 = *reinterpret_cast<const int4*>(g_tok + (m * BATCH + b) * 4);
        float s = 0.f;
        if (s4.x) s += __ldg(&g_proj[(size_t)s4.x * BATCH + b]);
        if (s4.y) s += __ldg(&g_proj[(size_t)s4.y * BATCH + b]);
        if (s4.z) s += __ldg(&g_proj[(size_t)s4.z * BATCH + b]);
        if (s4.w) s += __ldg(&g_proj[(size_t)s4.w * BATCH + b]);
        sc[m] = s;
        lmax = fmaxf(lmax, s);
    }
    red[t] = lmax; __syncthreads();
    for (int s = 128; s > 0; s >>= 1) {
        if (t < s) red[t] = fmaxf(red[t], red[t + s]);
        __syncthreads();
    }
    float mx = red[0]; __syncthreads();
    float lsum = 0.f;
#pragma unroll
    for (int i = 0; i < 8; i++) {
        float e = expf(sc[t + i * 256] - mx);
        sc[t + i * 256] = e;
        lsum += e;
    }
    red[t] = lsum; __syncthreads();
    for (int s = 128; s > 0; s >>= 1) {
        if (t < s) red[t] += red[t + s];
        __syncthreads();
    }
    float inv = 1.0f / red[0];
#pragma unroll
    for (int i = 0; i < 8; i++)
        g_prob[b * MLEN + t + i * 256] = sc[t + i * 256] * inv;
}

// ---------------- K5: scatter probs into (L2-hot) w[b][v] --------------------
__global__ void k_scatter_prob() {
    int t = blockIdx.x * blockDim.x + threadIdx.x;
    if (t >= NTOK) return;
    int b = (t >> 2) & (BATCH - 1);
    int m = t >> 8;
    int tok = g_tok[t];
    if (tok) {
        float p = g_prob[b * MLEN + m];
        atomicAdd(&g_w[b * V + tok], p);
    }
}

// ---------------- K6: o partials = w[b][v] @ C[v][d] via mma.sync ------------
// A = w (row-major, v-contig). B = C transposed in staging -> [d][v].
#define GPS 24   // padded v-stride (bf16 units)
__global__ __launch_bounds__(256) void k_gemm2_mma(const float* __restrict__ Ct) {
    __shared__ __align__(16) __nv_bfloat16 Ah[64 * GPS], Al[64 * GPS];
    __shared__ __align__(16) __nv_bfloat16 Bh[128 * GPS], Bl[128 * GPS];
    int tid = threadIdx.x;
    int wid = tid >> 5, lane = tid & 31;
    int g = lane >> 2, tig = lane & 3;
    int mw = wid & 3, nw = wid >> 2;
    int s0 = (int)((long long)blockIdx.x * NSTEPS / NPART);
    int s1 = (int)((long long)(blockIdx.x + 1) * NSTEPS / NPART);

    float acc[8][4];
#pragma unroll
    for (int i = 0; i < 8; i++)
#pragma unroll
        for (int j = 0; j < 4; j++) acc[i][j] = 0.f;

    float pa[4], pb[8];
    {   // prefetch s0
        int vb = s0 * 16;
#pragma unroll
        for (int i = 0; i < 4; i++) {
            int e = tid + i * 256;           // 1024: b = e>>4, j = e&15
            pa[i] = g_w[(size_t)(e >> 4) * V + vb + (e & 15)];
        }
#pragma unroll
        for (int i = 0; i < 8; i++) {
            int e = tid + i * 256;           // 2048: j = e>>7, d = e&127
            pb[i] = Ct[(size_t)(vb + (e >> 7)) * DIM + (e & 127)];
        }
    }

    for (int s = s0; s < s1; s++) {
        // store staged tiles (A: [b][j], B transposed: [d][j])
#pragma unroll
        for (int i = 0; i < 4; i++) {
            int e = tid + i * 256;
            int b = e >> 4, j = e & 15;
            __nv_bfloat16 h = __float2bfloat16(pa[i]);
            Ah[b * GPS + j] = h;
            Al[b * GPS + j] = __float2bfloat16(pa[i] - __bfloat162float(h));
        }
#pragma unroll
        for (int i = 0; i < 8; i++) {
            int e = tid + i * 256;
            int j = e >> 7, d = e & 127;
            __nv_bfloat16 h = __float2bfloat16(pb[i]);
            Bh[d * GPS + j] = h;
            Bl[d * GPS + j] = __float2bfloat16(pb[i] - __bfloat162float(h));
        }
        __syncthreads();
        if (s + 1 < s1) {                    // prefetch next (hidden by mma)
            int vb = (s + 1) * 16;
#pragma unroll
            for (int i = 0; i < 4; i++) {
                int e = tid + i * 256;
                pa[i] = g_w[(size_t)(e >> 4) * V + vb + (e & 15)];
            }
#pragma unroll
            for (int i = 0; i < 8; i++) {
                int e = tid + i * 256;
                pb[i] = Ct[(size_t)(vb + (e >> 7)) * DIM + (e & 127)];
            }
        }
        int arow = mw * 16 + g;
        int ko = 2 * tig;
        uint32_t ah0 = *reinterpret_cast<uint32_t*>(&Ah[arow * GPS + ko]);
        uint32_t ah1 = *reinterpret_cast<uint32_t*>(&Ah[(arow + 8) * GPS + ko]);
        uint32_t ah2 = *reinterpret_cast<uint32_t*>(&Ah[arow * GPS + ko + 8]);
        uint32_t ah3 = *reinterpret_cast<uint32_t*>(&Ah[(arow + 8) * GPS + ko + 8]);
        uint32_t al0 = *reinterpret_cast<uint32_t*>(&Al[arow * GPS + ko]);
        uint32_t al1 = *reinterpret_cast<uint32_t*>(&Al[(arow + 8) * GPS + ko]);
        uint32_t al2 = *reinterpret_cast<uint32_t*>(&Al[arow * GPS + ko + 8]);
        uint32_t al3 = *reinterpret_cast<uint32_t*>(&Al[(arow + 8) * GPS + ko + 8]);
#pragma unroll
        for (int nt = 0; nt < 8; nt++) {
            int d = nw * 64 + nt * 8 + g;
            uint32_t bh0 = *reinterpret_cast<uint32_t*>(&Bh[d * GPS + ko]);
            uint32_t bh1 = *reinterpret_cast<uint32_t*>(&Bh[d * GPS + ko + 8]);
            uint32_t bl0 = *reinterpret_cast<uint32_t*>(&Bl[d * GPS + ko]);
            uint32_t bl1 = *reinterpret_cast<uint32_t*>(&Bl[d * GPS + ko + 8]);
            mma_bf16(acc[nt], ah0, ah1, ah2, ah3, bh0, bh1);
            mma_bf16(acc[nt], ah0, ah1, ah2, ah3, bl0, bl1);
            mma_bf16(acc[nt], al0, al1, al2, al3, bh0, bh1);
        }
        __syncthreads();
    }
    float* pp = g_part + (size_t)blockIdx.x * (BATCH * DIM);
    int bA = mw * 16 + g, bB = bA + 8;
#pragma unroll
    for (int nt = 0; nt < 8; nt++) {
        int d = nw * 64 + nt * 8 + 2 * tig;
        *reinterpret_cast<float2*>(&pp[bA * DIM + d]) =
            make_float2(acc[nt][0], acc[nt][1]);
        *reinterpret_cast<float2*>(&pp[bB * DIM + d]) =
            make_float2(acc[nt][2], acc[nt][3]);
    }
}

// ---------------- K7: reduce partials + update u + re-zero w -----------------
__global__ void k_reduce(float scale, float* out, int zerow) {
    if (blockIdx.x < 32) {
        int i = blockIdx.x * blockDim.x + threadIdx.x;   // 8192
        float s = 0.f;
        int k = 0;
#pragma unroll
        for (; k + 8 <= NPART; k += 8) {
            float a0 = g_part[(size_t)(k + 0) * (BATCH * DIM) + i];
            float a1 = g_part[(size_t)(k + 1) * (BATCH * DIM) + i];
            float a2 = g_part[(size_t)(k + 2) * (BATCH * DIM) + i];
            float a3 = g_part[(size_t)(k + 3) * (BATCH * DIM) + i];
            float a4 = g_part[(size_t)(k + 4) * (BATCH * DIM) + i];
            float a5 = g_part[(size_t)(k + 5) * (BATCH * DIM) + i];
            float a6 = g_part[(size_t)(k + 6) * (BATCH * DIM) + i];
            float a7 = g_part[(size_t)(k + 7) * (BATCH * DIM) + i];
            s += ((a0 + a1) + (a2 + a3)) + ((a4 + a5) + (a6 + a7));
        }
        for (; k < NPART; k++) s += g_part[(size_t)k * (BATCH * DIM) + i];
        float un = g_u[i] + scale * s;
        g_u[i] = un;
        if (out) out[i] = un;
    } else if (zerow) {
        const float4 z = make_float4(0.f, 0.f, 0.f, 0.f);
        int t0 = (blockIdx.x - 32) * blockDim.x + threadIdx.x;
        int stride = (gridDim.x - 32) * blockDim.x;
        float4* w4 = reinterpret_cast<float4*>(g_w);
        for (int i = t0; i < V * BATCH / 4; i += stride) w4[i] = z;
    }
}

// -----------------------------------------------------------------------------
extern "C" void kernel_launch(void* const* d_in, const int* in_sizes, int n_in,
                              void* d_out, int out_size) {
    const void* story;
    const float* C;
    if (in_sizes[0] == NTOK) {
        story = d_in[0];
        C = (const float*)d_in[1];
    } else {
        story = d_in[1];
        C = (const float*)d_in[0];
    }
    float* out = (float*)d_out;
    const float* C1 = C + (size_t)1 * V * DIM;
    const float* C2 = C + (size_t)2 * V * DIM;
    const float* C3 = C + (size_t)3 * V * DIM;

    static int attr_set = 0;
    if (!attr_set) {
        cudaFuncSetAttribute(k_proj_mma,
                             cudaFuncAttributeMaxDynamicSharedMemorySize,
                             PROJ_SMEM);
        attr_set = 1;
    }

    const int PROJ_BLKS = (V + 127) / 128;   // 391
    const int TOK_BLKS = NTOK / 256;         // 2048

    k_zero<<<512, 256>>>();
    k_detect<<<16, 256>>>((const unsigned*)story);
    k_prep<<<TOK_BLKS, 256>>>((const int*)story);

    // hop 0: uniform softmax -> u1 = (1/M) * counts @ C1
    k_gemm2_mma<<<NPART, 256>>>(C1);
    k_reduce<<<512, 256>>>(1.0f / (float)MLEN, nullptr, 1);

    // hop 1
    k_proj_mma<<<PROJ_BLKS, 256, PROJ_SMEM>>>(C1);
    k_scores_smax<<<BATCH, 256>>>();
    k_scatter_prob<<<TOK_BLKS, 256>>>();
    k_gemm2_mma<<<NPART, 256>>>(C2);
    k_reduce<<<512, 256>>>(1.0f, nullptr, 1);

    // hop 2
    k_proj_mma<<<PROJ_BLKS, 256, PROJ_SMEM>>>(C2);
    k_scores_smax<<<BATCH, 256>>>();
    k_scatter_prob<<<TOK_BLKS, 256>>>();
    k_gemm2_mma<<<NPART, 256>>>(C3);
    k_reduce<<<32, 256>>>(1.0f, out, 0);
}

// round 12
// speedup vs baseline: 1.5856x; 1.0861x over previous
#include <cuda_runtime.h>
#include <cuda_bf16.h>
#include <cstdint>

#define V      50000
#define BATCH  64
#define MLEN   2048
#define DIM    128
#define NPART  296
#define NSTEPS 3125   // V/16 exactly
#define NTOK   (MLEN * BATCH * 4)   // 524288 tokens

// ---------------- scratch (device globals; no allocs allowed) ----------------
__device__ float g_w[V * BATCH];              // w[b][v] (12.8 MB, L2-hot)
__device__ float g_proj[V * BATCH];           // proj[v][b] (12.8 MB)
__device__ float g_u[BATCH * DIM];            // running u [b][d]
__device__ float g_part[NPART * BATCH * DIM]; // split-K partials (9.7 MB)
__device__ int   g_tok[NTOK];                 // normalized int32 tokens (2 MB)
__device__ int   g_is32;

// ---------------- mma.sync bf16 (sm_80+ PTX, works on sm_103 base) -----------
__device__ __forceinline__ void mma_bf16(float* d, uint32_t a0, uint32_t a1,
                                         uint32_t a2, uint32_t a3,
                                         uint32_t b0, uint32_t b1) {
    asm volatile(
        "mma.sync.aligned.m16n8k16.row.col.f32.bf16.bf16.f32 "
        "{%0,%1,%2,%3}, {%4,%5,%6,%7}, {%8,%9}, {%0,%1,%2,%3};"
        : "+f"(d[0]), "+f"(d[1]), "+f"(d[2]), "+f"(d[3])
        : "r"(a0), "r"(a1), "r"(a2), "r"(a3), "r"(b0), "r"(b1));
}
// split fp32 -> (bf16 hi, bf16 lo)
__device__ __forceinline__ void split2(float x, float y, uint32_t& hi,
                                       uint32_t& lo) {
    __nv_bfloat16 hx = __float2bfloat16(x), hy = __float2bfloat16(y);
    __nv_bfloat162 H = __halves2bfloat162(hx, hy);
    __nv_bfloat162 L = __halves2bfloat162(
        __float2bfloat16(x - __bfloat162float(hx)),
        __float2bfloat16(y - __bfloat162float(hy)));
    hi = *reinterpret_cast<uint32_t*>(&H);
    lo = *reinterpret_cast<uint32_t*>(&L);
}

// ---------------- K0: zero w + u + flag --------------------------------------
__global__ void k_zero() {
    const float4 z = make_float4(0.f, 0.f, 0.f, 0.f);
    int t = blockIdx.x * blockDim.x + threadIdx.x;
    int stride = gridDim.x * blockDim.x;
    float4* w4 = reinterpret_cast<float4*>(g_w);
    for (int i = t; i < V * BATCH / 4; i += stride) w4[i] = z;
    if (t < (BATCH * DIM / 4)) reinterpret_cast<float4*>(g_u)[t] = z;
    if (t == 0) g_is32 = 0;
}

// ---------------- K0b: dtype probe -------------------------------------------
__global__ void k_detect(const unsigned* __restrict__ s) {
    int t = blockIdx.x * blockDim.x + threadIdx.x;   // 4096 threads
    if (s[2 * t + 1] != 0u) g_is32 = 1;
}

// ---------------- K0c: convert story + scatter hop0 counts (fused) -----------
__global__ void k_prep(const int* __restrict__ s) {
    int t = blockIdx.x * blockDim.x + threadIdx.x;
    if (t >= NTOK) return;
    int tok = g_is32 ? s[t] : s[2 * t];   // int64 LE: low word at 2*t
    g_tok[t] = tok;
    if (tok) {
        int b = (t >> 2) & (BATCH - 1);
        atomicAdd(&g_w[b * V + tok], 1.0f);
    }
}

// ---------------- K2: proj[v][b] = C[v][:] . u[b][:] via mma.sync ------------
#define PPS 136                       // padded k-stride (bf16 units)
#define A_HI_OFF 0
#define A_LO_OFF 34816                // 128*136*2
#define B_HI_OFF 69632
#define B_LO_OFF 87040                // +64*136*2
#define PROJ_SMEM 104448

__global__ __launch_bounds__(256) void k_proj_mma(const float* __restrict__ Ct) {
    extern __shared__ __align__(16) char sm[];
    int tid = threadIdx.x;
    int wid = tid >> 5, lane = tid & 31;
    int g = lane >> 2, tig = lane & 3;
    int v0 = blockIdx.x * 128;

#pragma unroll
    for (int i = 0; i < 32; i++) {
        int p = tid + i * 256;            // 8192 k-pairs of A
        int row = p >> 6, kp = p & 63;
        int gv = v0 + row;
        float2 c = make_float2(0.f, 0.f);
        if (gv < V)
            c = *reinterpret_cast<const float2*>(Ct + (size_t)gv * DIM + 2 * kp);
        uint32_t hi, lo;
        split2(c.x, c.y, hi, lo);
        int off = 4 * (row * (PPS / 2) + kp);
        *reinterpret_cast<uint32_t*>(sm + A_HI_OFF + off) = hi;
        *reinterpret_cast<uint32_t*>(sm + A_LO_OFF + off) = lo;
    }
#pragma unroll
    for (int i = 0; i < 16; i++) {
        int p = tid + i * 256;            // 4096 k-pairs of B (u)
        int row = p >> 6, kp = p & 63;
        float2 c = *reinterpret_cast<const float2*>(g_u + row * DIM + 2 * kp);
        uint32_t hi, lo;
        split2(c.x, c.y, hi, lo);
        int off = 4 * (row * (PPS / 2) + kp);
        *reinterpret_cast<uint32_t*>(sm + B_HI_OFF + off) = hi;
        *reinterpret_cast<uint32_t*>(sm + B_LO_OFF + off) = lo;
    }
    __syncthreads();

    float acc[8][4];
#pragma unroll
    for (int i = 0; i < 8; i++)
#pragma unroll
        for (int j = 0; j < 4; j++) acc[i][j] = 0.f;

    int arow = wid * 16 + g;
#pragma unroll
    for (int ks = 0; ks < 8; ks++) {
        int ao = ks * 16 + 2 * tig;
        uint32_t ah0 = *reinterpret_cast<uint32_t*>(sm + A_HI_OFF + 2 * (arow * PPS + ao));
        uint32_t ah1 = *reinterpret_cast<uint32_t*>(sm + A_HI_OFF + 2 * ((arow + 8) * PPS + ao));
        uint32_t ah2 = *reinterpret_cast<uint32_t*>(sm + A_HI_OFF + 2 * (arow * PPS + ao + 8));
        uint32_t ah3 = *reinterpret_cast<uint32_t*>(sm + A_HI_OFF + 2 * ((arow + 8) * PPS + ao + 8));
        uint32_t al0 = *reinterpret_cast<uint32_t*>(sm + A_LO_OFF + 2 * (arow * PPS + ao));
        uint32_t al1 = *reinterpret_cast<uint32_t*>(sm + A_LO_OFF + 2 * ((arow + 8) * PPS + ao));
        uint32_t al2 = *reinterpret_cast<uint32_t*>(sm + A_LO_OFF + 2 * (arow * PPS + ao + 8));
        uint32_t al3 = *reinterpret_cast<uint32_t*>(sm + A_LO_OFF + 2 * ((arow + 8) * PPS + ao + 8));
#pragma unroll
        for (int nt = 0; nt < 8; nt++) {
            int bcol = nt * 8 + g;
            uint32_t bh0 = *reinterpret_cast<uint32_t*>(sm + B_HI_OFF + 2 * (bcol * PPS + ao));
            uint32_t bh1 = *reinterpret_cast<uint32_t*>(sm + B_HI_OFF + 2 * (bcol * PPS + ao + 8));
            uint32_t bl0 = *reinterpret_cast<uint32_t*>(sm + B_LO_OFF + 2 * (bcol * PPS + ao));
            uint32_t bl1 = *reinterpret_cast<uint32_t*>(sm + B_LO_OFF + 2 * (bcol * PPS + ao + 8));
            mma_bf16(acc[nt], ah0, ah1, ah2, ah3, bh0, bh1);
            mma_bf16(acc[nt], ah0, ah1, ah2, ah3, bl0, bl1);
            mma_bf16(acc[nt], al0, al1, al2, al3, bh0, bh1);
        }
    }
    int vA = v0 + arow, vB = vA + 8;
#pragma unroll
    for (int nt = 0; nt < 8; nt++) {
        int col = nt * 8 + 2 * tig;
        if (vA < V)
            *reinterpret_cast<float2*>(&g_proj[(size_t)vA * BATCH + col]) =
                make_float2(acc[nt][0], acc[nt][1]);
        if (vB < V)
            *reinterpret_cast<float2*>(&g_proj[(size_t)vB * BATCH + col]) =
                make_float2(acc[nt][2], acc[nt][3]);
    }
}

// ---------------- K3: scores + softmax + prob-scatter fused (block = b) ------
__global__ void k_scores_smax_scatter() {
    __shared__ __align__(16) float sc[MLEN];
    __shared__ float red[256];
    int b = blockIdx.x, t = threadIdx.x;
    float lmax = -1e30f;
#pragma unroll
    for (int i = 0; i < 8; i++) {
        int m = i * 256 + t;
        int4 s4 = *reinterpret_cast<const int4*>(g_tok + (m * BATCH + b) * 4);
        float s = 0.f;
        if (s4.x) s += __ldg(&g_proj[(size_t)s4.x * BATCH + b]);
        if (s4.y) s += __ldg(&g_proj[(size_t)s4.y * BATCH + b]);
        if (s4.z) s += __ldg(&g_proj[(size_t)s4.z * BATCH + b]);
        if (s4.w) s += __ldg(&g_proj[(size_t)s4.w * BATCH + b]);
        sc[m] = s;
        lmax = fmaxf(lmax, s);
    }
    red[t] = lmax; __syncthreads();
    for (int s = 128; s > 0; s >>= 1) {
        if (t < s) red[t] = fmaxf(red[t], red[t + s]);
        __syncthreads();
    }
    float mx = red[0]; __syncthreads();
    float lsum = 0.f;
#pragma unroll
    for (int i = 0; i < 8; i++) {
        float e = expf(sc[t + i * 256] - mx);
        sc[t + i * 256] = e;
        lsum += e;
    }
    red[t] = lsum; __syncthreads();
    for (int s = 128; s > 0; s >>= 1) {
        if (t < s) red[t] += red[t + s];
        __syncthreads();
    }
    float inv = 1.0f / red[0];
    // scatter this block's probs straight into w[b][*]
    float* wb = g_w + (size_t)b * V;
#pragma unroll
    for (int i = 0; i < 8; i++) {
        int m = i * 256 + t;
        float p = sc[m] * inv;
        int4 s4 = *reinterpret_cast<const int4*>(g_tok + (m * BATCH + b) * 4);
        if (s4.x) atomicAdd(&wb[s4.x], p);
        if (s4.y) atomicAdd(&wb[s4.y], p);
        if (s4.z) atomicAdd(&wb[s4.z], p);
        if (s4.w) atomicAdd(&wb[s4.w], p);
    }
}

// ---------------- K6: o partials = w[b][v] @ C[v][d] via mma.sync ------------
// 2 CTAs/SM (NPART=296) for latency cover. B = C transposed in staging.
#define GPS 24   // padded v-stride (bf16 units)
__global__ __launch_bounds__(256, 2) void k_gemm2_mma(const float* __restrict__ Ct) {
    __shared__ __align__(16) __nv_bfloat16 Ah[64 * GPS], Al[64 * GPS];
    __shared__ __align__(16) __nv_bfloat16 Bh[128 * GPS], Bl[128 * GPS];
    int tid = threadIdx.x;
    int wid = tid >> 5, lane = tid & 31;
    int g = lane >> 2, tig = lane & 3;
    int mw = wid & 3, nw = wid >> 2;
    int s0 = (int)((long long)blockIdx.x * NSTEPS / NPART);
    int s1 = (int)((long long)(blockIdx.x + 1) * NSTEPS / NPART);

    float acc[8][4];
#pragma unroll
    for (int i = 0; i < 8; i++)
#pragma unroll
        for (int j = 0; j < 4; j++) acc[i][j] = 0.f;

    float pa[4], pb[8];
    {   // prefetch s0
        int vb = s0 * 16;
#pragma unroll
        for (int i = 0; i < 4; i++) {
            int e = tid + i * 256;
            pa[i] = g_w[(size_t)(e >> 4) * V + vb + (e & 15)];
        }
#pragma unroll
        for (int i = 0; i < 8; i++) {
            int e = tid + i * 256;
            pb[i] = Ct[(size_t)(vb + (e >> 7)) * DIM + (e & 127)];
        }
    }

    for (int s = s0; s < s1; s++) {
#pragma unroll
        for (int i = 0; i < 4; i++) {
            int e = tid + i * 256;
            int b = e >> 4, j = e & 15;
            __nv_bfloat16 h = __float2bfloat16(pa[i]);
            Ah[b * GPS + j] = h;
            Al[b * GPS + j] = __float2bfloat16(pa[i] - __bfloat162float(h));
        }
#pragma unroll
        for (int i = 0; i < 8; i++) {
            int e = tid + i * 256;
            int j = e >> 7, d = e & 127;
            __nv_bfloat16 h = __float2bfloat16(pb[i]);
            Bh[d * GPS + j] = h;
            Bl[d * GPS + j] = __float2bfloat16(pb[i] - __bfloat162float(h));
        }
        __syncthreads();
        if (s + 1 < s1) {
            int vb = (s + 1) * 16;
#pragma unroll
            for (int i = 0; i < 4; i++) {
                int e = tid + i * 256;
                pa[i] = g_w[(size_t)(e >> 4) * V + vb + (e & 15)];
            }
#pragma unroll
            for (int i = 0; i < 8; i++) {
                int e = tid + i * 256;
                pb[i] = Ct[(size_t)(vb + (e >> 7)) * DIM + (e & 127)];
            }
        }
        int arow = mw * 16 + g;
        int ko = 2 * tig;
        uint32_t ah0 = *reinterpret_cast<uint32_t*>(&Ah[arow * GPS + ko]);
        uint32_t ah1 = *reinterpret_cast<uint32_t*>(&Ah[(arow + 8) * GPS + ko]);
        uint32_t ah2 = *reinterpret_cast<uint32_t*>(&Ah[arow * GPS + ko + 8]);
        uint32_t ah3 = *reinterpret_cast<uint32_t*>(&Ah[(arow + 8) * GPS + ko + 8]);
        uint32_t al0 = *reinterpret_cast<uint32_t*>(&Al[arow * GPS + ko]);
        uint32_t al1 = *reinterpret_cast<uint32_t*>(&Al[(arow + 8) * GPS + ko]);
        uint32_t al2 = *reinterpret_cast<uint32_t*>(&Al[arow * GPS + ko + 8]);
        uint32_t al3 = *reinterpret_cast<uint32_t*>(&Al[(arow + 8) * GPS + ko + 8]);
#pragma unroll
        for (int nt = 0; nt < 8; nt++) {
            int d = nw * 64 + nt * 8 + g;
            uint32_t bh0 = *reinterpret_cast<uint32_t*>(&Bh[d * GPS + ko]);
            uint32_t bh1 = *reinterpret_cast<uint32_t*>(&Bh[d * GPS + ko + 8]);
            uint32_t bl0 = *reinterpret_cast<uint32_t*>(&Bl[d * GPS + ko]);
            uint32_t bl1 = *reinterpret_cast<uint32_t*>(&Bl[d * GPS + ko + 8]);
            mma_bf16(acc[nt], ah0, ah1, ah2, ah3, bh0, bh1);
            mma_bf16(acc[nt], ah0, ah1, ah2, ah3, bl0, bl1);
            mma_bf16(acc[nt], al0, al1, al2, al3, bh0, bh1);
        }
        __syncthreads();
    }
    float* pp = g_part + (size_t)blockIdx.x * (BATCH * DIM);
    int bA = mw * 16 + g, bB = bA + 8;
#pragma unroll
    for (int nt = 0; nt < 8; nt++) {
        int d = nw * 64 + nt * 8 + 2 * tig;
        *reinterpret_cast<float2*>(&pp[bA * DIM + d]) =
            make_float2(acc[nt][0], acc[nt][1]);
        *reinterpret_cast<float2*>(&pp[bB * DIM + d]) =
            make_float2(acc[nt][2], acc[nt][3]);
    }
}

// ---------------- K7: reduce partials + update u + re-zero w -----------------
__global__ void k_reduce(float scale, float* out, int zerow) {
    if (blockIdx.x < 32) {
        int i = blockIdx.x * blockDim.x + threadIdx.x;   // 8192
        float s = 0.f;
        int k = 0;
#pragma unroll
        for (; k + 8 <= NPART; k += 8) {
            float a0 = g_part[(size_t)(k + 0) * (BATCH * DIM) + i];
            float a1 = g_part[(size_t)(k + 1) * (BATCH * DIM) + i];
            float a2 = g_part[(size_t)(k + 2) * (BATCH * DIM) + i];
            float a3 = g_part[(size_t)(k + 3) * (BATCH * DIM) + i];
            float a4 = g_part[(size_t)(k + 4) * (BATCH * DIM) + i];
            float a5 = g_part[(size_t)(k + 5) * (BATCH * DIM) + i];
            float a6 = g_part[(size_t)(k + 6) * (BATCH * DIM) + i];
            float a7 = g_part[(size_t)(k + 7) * (BATCH * DIM) + i];
            s += ((a0 + a1) + (a2 + a3)) + ((a4 + a5) + (a6 + a7));
        }
        for (; k < NPART; k++) s += g_part[(size_t)k * (BATCH * DIM) + i];
        float un = g_u[i] + scale * s;
        g_u[i] = un;
        if (out) out[i] = un;
    } else if (zerow) {
        const float4 z = make_float4(0.f, 0.f, 0.f, 0.f);
        int t0 = (blockIdx.x - 32) * blockDim.x + threadIdx.x;
        int stride = (gridDim.x - 32) * blockDim.x;
        float4* w4 = reinterpret_cast<float4*>(g_w);
        for (int i = t0; i < V * BATCH / 4; i += stride) w4[i] = z;
    }
}

// -----------------------------------------------------------------------------
extern "C" void kernel_launch(void* const* d_in, const int* in_sizes, int n_in,
                              void* d_out, int out_size) {
    const void* story;
    const float* C;
    if (in_sizes[0] == NTOK) {
        story = d_in[0];
        C = (const float*)d_in[1];
    } else {
        story = d_in[1];
        C = (const float*)d_in[0];
    }
    float* out = (float*)d_out;
    const float* C1 = C + (size_t)1 * V * DIM;
    const float* C2 = C + (size_t)2 * V * DIM;
    const float* C3 = C + (size_t)3 * V * DIM;

    static int attr_set = 0;
    if (!attr_set) {
        cudaFuncSetAttribute(k_proj_mma,
                             cudaFuncAttributeMaxDynamicSharedMemorySize,
                             PROJ_SMEM);
        attr_set = 1;
    }

    const int PROJ_BLKS = (V + 127) / 128;   // 391
    const int TOK_BLKS = NTOK / 256;         // 2048

    k_zero<<<512, 256>>>();
    k_detect<<<16, 256>>>((const unsigned*)story);
    k_prep<<<TOK_BLKS, 256>>>((const int*)story);

    // hop 0: uniform softmax -> u1 = (1/M) * counts @ C1
    k_gemm2_mma<<<NPART, 256>>>(C1);
    k_reduce<<<512, 256>>>(1.0f / (float)MLEN, nullptr, 1);

    // hop 1
    k_proj_mma<<<PROJ_BLKS, 256, PROJ_SMEM>>>(C1);
    k_scores_smax_scatter<<<BATCH, 256>>>();
    k_gemm2_mma<<<NPART, 256>>>(C2);
    k_reduce<<<512, 256>>>(1.0f, nullptr, 1);

    // hop 2
    k_proj_mma<<<PROJ_BLKS, 256, PROJ_SMEM>>>(C2);
    k_scores_smax_scatter<<<BATCH, 256>>>();
    k_gemm2_mma<<<NPART, 256>>>(C3);
    k_reduce<<<32, 256>>>(1.0f, out, 0);
}

// round 13
// speedup vs baseline: 1.6489x; 1.0399x over previous
#include <cuda_runtime.h>
#include <cuda_bf16.h>
#include <cstdint>

#define V      50000
#define BATCH  64
#define MLEN   2048
#define DIM    128
#define NPART  296
#define NSTEPS 3125   // V/16 exactly
#define NTOK   (MLEN * BATCH * 4)   // 524288 tokens

// ---------------- scratch (device globals; no allocs allowed) ----------------
__device__ float g_w[V * BATCH];              // w[b][v] (12.8 MB, L2-hot)
__device__ float g_proj[V * BATCH];           // proj[v][b] (12.8 MB)
__device__ float g_u[BATCH * DIM];            // running u [b][d]
__device__ float g_part[NPART * BATCH * DIM]; // split-K partials (9.7 MB)
__device__ int   g_tok[NTOK];                 // normalized int32 tokens (2 MB)
__device__ int   g_is32;

// ---------------- mma.sync bf16 (sm_80+ PTX, works on sm_103 base) -----------
__device__ __forceinline__ void mma_bf16(float* d, uint32_t a0, uint32_t a1,
                                         uint32_t a2, uint32_t a3,
                                         uint32_t b0, uint32_t b1) {
    asm volatile(
        "mma.sync.aligned.m16n8k16.row.col.f32.bf16.bf16.f32 "
        "{%0,%1,%2,%3}, {%4,%5,%6,%7}, {%8,%9}, {%0,%1,%2,%3};"
        : "+f"(d[0]), "+f"(d[1]), "+f"(d[2]), "+f"(d[3])
        : "r"(a0), "r"(a1), "r"(a2), "r"(a3), "r"(b0), "r"(b1));
}
__device__ __forceinline__ void split2(float x, float y, uint32_t& hi,
                                       uint32_t& lo) {
    __nv_bfloat16 hx = __float2bfloat16(x), hy = __float2bfloat16(y);
    __nv_bfloat162 H = __halves2bfloat162(hx, hy);
    __nv_bfloat162 L = __halves2bfloat162(
        __float2bfloat16(x - __bfloat162float(hx)),
        __float2bfloat16(y - __bfloat162float(hy)));
    hi = *reinterpret_cast<uint32_t*>(&H);
    lo = *reinterpret_cast<uint32_t*>(&L);
}

// ---------------- K0: zero w + u + flag --------------------------------------
__global__ void k_zero() {
    const float4 z = make_float4(0.f, 0.f, 0.f, 0.f);
    int t = blockIdx.x * blockDim.x + threadIdx.x;
    int stride = gridDim.x * blockDim.x;
    float4* w4 = reinterpret_cast<float4*>(g_w);
    for (int i = t; i < V * BATCH / 4; i += stride) w4[i] = z;
    if (t < (BATCH * DIM / 4)) reinterpret_cast<float4*>(g_u)[t] = z;
    if (t == 0) g_is32 = 0;
}

// ---------------- K0b: dtype probe -------------------------------------------
__global__ void k_detect(const unsigned* __restrict__ s) {
    int t = blockIdx.x * blockDim.x + threadIdx.x;   // 4096 threads
    if (s[2 * t + 1] != 0u) g_is32 = 1;
}

// ---------------- K0c: convert story + scatter hop0 counts (fused) -----------
__global__ void k_prep(const int* __restrict__ s) {
    int t = blockIdx.x * blockDim.x + threadIdx.x;
    if (t >= NTOK) return;
    int tok = g_is32 ? s[t] : s[2 * t];   // int64 LE: low word at 2*t
    g_tok[t] = tok;
    if (tok) {
        int b = (t >> 2) & (BATCH - 1);
        atomicAdd(&g_w[b * V + tok], 1.0f);
    }
}

// ---------------- K2: proj[v][b] = C[v][:] . u[b][:] via mma.sync ------------
#define PPS 136                       // padded k-stride (bf16 units)
#define A_HI_OFF 0
#define A_LO_OFF 34816                // 128*136*2
#define B_HI_OFF 69632
#define B_LO_OFF 87040                // +64*136*2
#define PROJ_SMEM 104448

__global__ __launch_bounds__(256, 2) void k_proj_mma(const float* __restrict__ Ct) {
    extern __shared__ __align__(16) char sm[];
    int tid = threadIdx.x;
    int wid = tid >> 5, lane = tid & 31;
    int g = lane >> 2, tig = lane & 3;
    int v0 = blockIdx.x * 128;

#pragma unroll
    for (int i = 0; i < 32; i++) {
        int p = tid + i * 256;            // 8192 k-pairs of A
        int row = p >> 6, kp = p & 63;
        int gv = v0 + row;
        float2 c = make_float2(0.f, 0.f);
        if (gv < V)
            c = *reinterpret_cast<const float2*>(Ct + (size_t)gv * DIM + 2 * kp);
        uint32_t hi, lo;
        split2(c.x, c.y, hi, lo);
        int off = 4 * (row * (PPS / 2) + kp);
        *reinterpret_cast<uint32_t*>(sm + A_HI_OFF + off) = hi;
        *reinterpret_cast<uint32_t*>(sm + A_LO_OFF + off) = lo;
    }
#pragma unroll
    for (int i = 0; i < 16; i++) {
        int p = tid + i * 256;            // 4096 k-pairs of B (u)
        int row = p >> 6, kp = p & 63;
        float2 c = *reinterpret_cast<const float2*>(g_u + row * DIM + 2 * kp);
        uint32_t hi, lo;
        split2(c.x, c.y, hi, lo);
        int off = 4 * (row * (PPS / 2) + kp);
        *reinterpret_cast<uint32_t*>(sm + B_HI_OFF + off) = hi;
        *reinterpret_cast<uint32_t*>(sm + B_LO_OFF + off) = lo;
    }
    __syncthreads();

    float acc[8][4];
#pragma unroll
    for (int i = 0; i < 8; i++)
#pragma unroll
        for (int j = 0; j < 4; j++) acc[i][j] = 0.f;

    int arow = wid * 16 + g;
#pragma unroll
    for (int ks = 0; ks < 8; ks++) {
        int ao = ks * 16 + 2 * tig;
        uint32_t ah0 = *reinterpret_cast<uint32_t*>(sm + A_HI_OFF + 2 * (arow * PPS + ao));
        uint32_t ah1 = *reinterpret_cast<uint32_t*>(sm + A_HI_OFF + 2 * ((arow + 8) * PPS + ao));
        uint32_t ah2 = *reinterpret_cast<uint32_t*>(sm + A_HI_OFF + 2 * (arow * PPS + ao + 8));
        uint32_t ah3 = *reinterpret_cast<uint32_t*>(sm + A_HI_OFF + 2 * ((arow + 8) * PPS + ao + 8));
        uint32_t al0 = *reinterpret_cast<uint32_t*>(sm + A_LO_OFF + 2 * (arow * PPS + ao));
        uint32_t al1 = *reinterpret_cast<uint32_t*>(sm + A_LO_OFF + 2 * ((arow + 8) * PPS + ao));
        uint32_t al2 = *reinterpret_cast<uint32_t*>(sm + A_LO_OFF + 2 * (arow * PPS + ao + 8));
        uint32_t al3 = *reinterpret_cast<uint32_t*>(sm + A_LO_OFF + 2 * ((arow + 8) * PPS + ao + 8));
#pragma unroll
        for (int nt = 0; nt < 8; nt++) {
            int bcol = nt * 8 + g;
            uint32_t bh0 = *reinterpret_cast<uint32_t*>(sm + B_HI_OFF + 2 * (bcol * PPS + ao));
            uint32_t bh1 = *reinterpret_cast<uint32_t*>(sm + B_HI_OFF + 2 * (bcol * PPS + ao + 8));
            uint32_t bl0 = *reinterpret_cast<uint32_t*>(sm + B_LO_OFF + 2 * (bcol * PPS + ao));
            uint32_t bl1 = *reinterpret_cast<uint32_t*>(sm + B_LO_OFF + 2 * (bcol * PPS + ao + 8));
            mma_bf16(acc[nt], ah0, ah1, ah2, ah3, bh0, bh1);
            mma_bf16(acc[nt], ah0, ah1, ah2, ah3, bl0, bl1);
            mma_bf16(acc[nt], al0, al1, al2, al3, bh0, bh1);
        }
    }
    int vA = v0 + arow, vB = vA + 8;
#pragma unroll
    for (int nt = 0; nt < 8; nt++) {
        int col = nt * 8 + 2 * tig;
        if (vA < V)
            *reinterpret_cast<float2*>(&g_proj[(size_t)vA * BATCH + col]) =
                make_float2(acc[nt][0], acc[nt][1]);
        if (vB < V)
            *reinterpret_cast<float2*>(&g_proj[(size_t)vB * BATCH + col]) =
                make_float2(acc[nt][2], acc[nt][3]);
    }
}

// ------- K3: scores + softmax + prob-scatter fused (block = b, 1024 thr) -----
__global__ __launch_bounds__(1024) void k_scores_smax_scatter() {
    __shared__ __align__(16) float sc[MLEN];
    __shared__ float red[32];
    int b = blockIdx.x, t = threadIdx.x;
    int lane = t & 31, warp = t >> 5;

    float lmax = -1e30f;
#pragma unroll
    for (int i = 0; i < 2; i++) {
        int m = i * 1024 + t;
        int4 s4 = *reinterpret_cast<const int4*>(g_tok + (m * BATCH + b) * 4);
        float s = 0.f;
        if (s4.x) s += __ldg(&g_proj[(size_t)s4.x * BATCH + b]);
        if (s4.y) s += __ldg(&g_proj[(size_t)s4.y * BATCH + b]);
        if (s4.z) s += __ldg(&g_proj[(size_t)s4.z * BATCH + b]);
        if (s4.w) s += __ldg(&g_proj[(size_t)s4.w * BATCH + b]);
        sc[m] = s;
        lmax = fmaxf(lmax, s);
    }
#pragma unroll
    for (int o = 16; o > 0; o >>= 1)
        lmax = fmaxf(lmax, __shfl_xor_sync(0xffffffffu, lmax, o));
    if (lane == 0) red[warp] = lmax;
    __syncthreads();
    if (t < 32) {
        float v = red[t];
#pragma unroll
        for (int o = 16; o > 0; o >>= 1)
            v = fmaxf(v, __shfl_xor_sync(0xffffffffu, v, o));
        if (t == 0) red[0] = v;
    }
    __syncthreads();
    float mx = red[0];
    __syncthreads();

    float lsum = 0.f;
#pragma unroll
    for (int i = 0; i < 2; i++) {
        int m = i * 1024 + t;
        float e = expf(sc[m] - mx);
        sc[m] = e;
        lsum += e;
    }
#pragma unroll
    for (int o = 16; o > 0; o >>= 1)
        lsum += __shfl_xor_sync(0xffffffffu, lsum, o);
    if (lane == 0) red[warp] = lsum;
    __syncthreads();
    if (t < 32) {
        float v = red[t];
#pragma unroll
        for (int o = 16; o > 0; o >>= 1)
            v += __shfl_xor_sync(0xffffffffu, v, o);
        if (t == 0) red[0] = v;
    }
    __syncthreads();
    float inv = 1.0f / red[0];

    float* wb = g_w + (size_t)b * V;
#pragma unroll
    for (int i = 0; i < 2; i++) {
        int m = i * 1024 + t;
        float p = sc[m] * inv;
        int4 s4 = *reinterpret_cast<const int4*>(g_tok + (m * BATCH + b) * 4);
        if (s4.x) atomicAdd(&wb[s4.x], p);
        if (s4.y) atomicAdd(&wb[s4.y], p);
        if (s4.z) atomicAdd(&wb[s4.z], p);
        if (s4.w) atomicAdd(&wb[s4.w], p);
    }
}

// ---------------- K6: o partials = w[b][v] @ C[v][d], double-buffered --------
#define GPS 24   // padded v-stride (bf16 units)
__global__ __launch_bounds__(256, 2) void k_gemm2_mma(const float* __restrict__ Ct) {
    __shared__ __align__(16) __nv_bfloat16 Ah[2][64 * GPS], Al[2][64 * GPS];
    __shared__ __align__(16) __nv_bfloat16 Bh[2][128 * GPS], Bl[2][128 * GPS];
    int tid = threadIdx.x;
    int wid = tid >> 5, lane = tid & 31;
    int g = lane >> 2, tig = lane & 3;
    int mw = wid & 3, nw = wid >> 2;
    int s0 = (int)((long long)blockIdx.x * NSTEPS / NPART);
    int s1 = (int)((long long)(blockIdx.x + 1) * NSTEPS / NPART);

    float acc[8][4];
#pragma unroll
    for (int i = 0; i < 8; i++)
#pragma unroll
        for (int j = 0; j < 4; j++) acc[i][j] = 0.f;

    float pa[4], pb[8];
    {   // prologue: load + convert + store stage 0
        int vb = s0 * 16;
#pragma unroll
        for (int i = 0; i < 4; i++) {
            int e = tid + i * 256;
            pa[i] = g_w[(size_t)(e >> 4) * V + vb + (e & 15)];
        }
#pragma unroll
        for (int i = 0; i < 8; i++) {
            int e = tid + i * 256;
            pb[i] = Ct[(size_t)(vb + (e >> 7)) * DIM + (e & 127)];
        }
#pragma unroll
        for (int i = 0; i < 4; i++) {
            int e = tid + i * 256;
            int bb = e >> 4, j = e & 15;
            __nv_bfloat16 h = __float2bfloat16(pa[i]);
            Ah[0][bb * GPS + j] = h;
            Al[0][bb * GPS + j] = __float2bfloat16(pa[i] - __bfloat162float(h));
        }
#pragma unroll
        for (int i = 0; i < 8; i++) {
            int e = tid + i * 256;
            int j = e >> 7, d = e & 127;
            __nv_bfloat16 h = __float2bfloat16(pb[i]);
            Bh[0][d * GPS + j] = h;
            Bl[0][d * GPS + j] = __float2bfloat16(pb[i] - __bfloat162float(h));
        }
        __syncthreads();
    }

    int arow = mw * 16 + g;
    int ko = 2 * tig;
    for (int s = s0; s < s1; s++) {
        int cur = (s - s0) & 1, nxt = cur ^ 1;
        bool more = (s + 1 < s1);
        if (more) {   // issue global loads early; land during MMA phase
            int vb = (s + 1) * 16;
#pragma unroll
            for (int i = 0; i < 4; i++) {
                int e = tid + i * 256;
                pa[i] = g_w[(size_t)(e >> 4) * V + vb + (e & 15)];
            }
#pragma unroll
            for (int i = 0; i < 8; i++) {
                int e = tid + i * 256;
                pb[i] = Ct[(size_t)(vb + (e >> 7)) * DIM + (e & 127)];
            }
        }
        // MMA from buf[cur]
        uint32_t ah0 = *reinterpret_cast<uint32_t*>(&Ah[cur][arow * GPS + ko]);
        uint32_t ah1 = *reinterpret_cast<uint32_t*>(&Ah[cur][(arow + 8) * GPS + ko]);
        uint32_t ah2 = *reinterpret_cast<uint32_t*>(&Ah[cur][arow * GPS + ko + 8]);
        uint32_t ah3 = *reinterpret_cast<uint32_t*>(&Ah[cur][(arow + 8) * GPS + ko + 8]);
        uint32_t al0 = *reinterpret_cast<uint32_t*>(&Al[cur][arow * GPS + ko]);
        uint32_t al1 = *reinterpret_cast<uint32_t*>(&Al[cur][(arow + 8) * GPS + ko]);
        uint32_t al2 = *reinterpret_cast<uint32_t*>(&Al[cur][arow * GPS + ko + 8]);
        uint32_t al3 = *reinterpret_cast<uint32_t*>(&Al[cur][(arow + 8) * GPS + ko + 8]);
#pragma unroll
        for (int nt = 0; nt < 8; nt++) {
            int d = nw * 64 + nt * 8 + g;
            uint32_t bh0 = *reinterpret_cast<uint32_t*>(&Bh[cur][d * GPS + ko]);
            uint32_t bh1 = *reinterpret_cast<uint32_t*>(&Bh[cur][d * GPS + ko + 8]);
            uint32_t bl0 = *reinterpret_cast<uint32_t*>(&Bl[cur][d * GPS + ko]);
            uint32_t bl1 = *reinterpret_cast<uint32_t*>(&Bl[cur][d * GPS + ko + 8]);
            mma_bf16(acc[nt], ah0, ah1, ah2, ah3, bh0, bh1);
            mma_bf16(acc[nt], ah0, ah1, ah2, ah3, bl0, bl1);
            mma_bf16(acc[nt], al0, al1, al2, al3, bh0, bh1);
        }
        if (more) {   // convert + store stage s+1 (overlaps other warps' MMAs)
#pragma unroll
            for (int i = 0; i < 4; i++) {
                int e = tid + i * 256;
                int bb = e >> 4, j = e & 15;
                __nv_bfloat16 h = __float2bfloat16(pa[i]);
                Ah[nxt][bb * GPS + j] = h;
                Al[nxt][bb * GPS + j] =
                    __float2bfloat16(pa[i] - __bfloat162float(h));
            }
#pragma unroll
            for (int i = 0; i < 8; i++) {
                int e = tid + i * 256;
                int j = e >> 7, d = e & 127;
                __nv_bfloat16 h = __float2bfloat16(pb[i]);
                Bh[nxt][d * GPS + j] = h;
                Bl[nxt][d * GPS + j] =
                    __float2bfloat16(pb[i] - __bfloat162float(h));
            }
        }
        __syncthreads();
    }
    float* pp = g_part + (size_t)blockIdx.x * (BATCH * DIM);
    int bA = mw * 16 + g, bB = bA + 8;
#pragma unroll
    for (int nt = 0; nt < 8; nt++) {
        int d = nw * 64 + nt * 8 + 2 * tig;
        *reinterpret_cast<float2*>(&pp[bA * DIM + d]) =
            make_float2(acc[nt][0], acc[nt][1]);
        *reinterpret_cast<float2*>(&pp[bB * DIM + d]) =
            make_float2(acc[nt][2], acc[nt][3]);
    }
}

// ---------------- K7: reduce partials + update u + re-zero w -----------------
__global__ void k_reduce(float scale, float* out, int zerow) {
    if (blockIdx.x < 32) {
        int i = blockIdx.x * blockDim.x + threadIdx.x;   // 8192
        float s = 0.f;
        int k = 0;
#pragma unroll
        for (; k + 8 <= NPART; k += 8) {
            float a0 = g_part[(size_t)(k + 0) * (BATCH * DIM) + i];
            float a1 = g_part[(size_t)(k + 1) * (BATCH * DIM) + i];
            float a2 = g_part[(size_t)(k + 2) * (BATCH * DIM) + i];
            float a3 = g_part[(size_t)(k + 3) * (BATCH * DIM) + i];
            float a4 = g_part[(size_t)(k + 4) * (BATCH * DIM) + i];
            float a5 = g_part[(size_t)(k + 5) * (BATCH * DIM) + i];
            float a6 = g_part[(size_t)(k + 6) * (BATCH * DIM) + i];
            float a7 = g_part[(size_t)(k + 7) * (BATCH * DIM) + i];
            s += ((a0 + a1) + (a2 + a3)) + ((a4 + a5) + (a6 + a7));
        }
        for (; k < NPART; k++) s += g_part[(size_t)k * (BATCH * DIM) + i];
        float un = g_u[i] + scale * s;
        g_u[i] = un;
        if (out) out[i] = un;
    } else if (zerow) {
        const float4 z = make_float4(0.f, 0.f, 0.f, 0.f);
        int t0 = (blockIdx.x - 32) * blockDim.x + threadIdx.x;
        int stride = (gridDim.x - 32) * blockDim.x;
        float4* w4 = reinterpret_cast<float4*>(g_w);
        for (int i = t0; i < V * BATCH / 4; i += stride) w4[i] = z;
    }
}

// -----------------------------------------------------------------------------
extern "C" void kernel_launch(void* const* d_in, const int* in_sizes, int n_in,
                              void* d_out, int out_size) {
    const void* story;
    const float* C;
    if (in_sizes[0] == NTOK) {
        story = d_in[0];
        C = (const float*)d_in[1];
    } else {
        story = d_in[1];
        C = (const float*)d_in[0];
    }
    float* out = (float*)d_out;
    const float* C1 = C + (size_t)1 * V * DIM;
    const float* C2 = C + (size_t)2 * V * DIM;
    const float* C3 = C + (size_t)3 * V * DIM;

    static int attr_set = 0;
    if (!attr_set) {
        cudaFuncSetAttribute(k_proj_mma,
                             cudaFuncAttributeMaxDynamicSharedMemorySize,
                             PROJ_SMEM);
        attr_set = 1;
    }

    const int PROJ_BLKS = (V + 127) / 128;   // 391
    const int TOK_BLKS = NTOK / 256;         // 2048

    k_zero<<<512, 256>>>();
    k_detect<<<16, 256>>>((const unsigned*)story);
    k_prep<<<TOK_BLKS, 256>>>((const int*)story);

    // hop 0: uniform softmax -> u1 = (1/M) * counts @ C1
    k_gemm2_mma<<<NPART, 256>>>(C1);
    k_reduce<<<512, 256>>>(1.0f / (float)MLEN, nullptr, 1);

    // hop 1
    k_proj_mma<<<PROJ_BLKS, 256, PROJ_SMEM>>>(C1);
    k_scores_smax_scatter<<<BATCH, 1024>>>();
    k_gemm2_mma<<<NPART, 256>>>(C2);
    k_reduce<<<512, 256>>>(1.0f, nullptr, 1);

    // hop 2
    k_proj_mma<<<PROJ_BLKS, 256, PROJ_SMEM>>>(C2);
    k_scores_smax_scatter<<<BATCH, 1024>>>();
    k_gemm2_mma<<<NPART, 256>>>(C3);
    k_reduce<<<32, 256>>>(1.0f, out, 0);
}

// round 14
// speedup vs baseline: 1.8918x; 1.1473x over previous
#include <cuda_runtime.h>
#include <cuda_bf16.h>
#include <cstdint>

#define V      50000
#define BATCH  64
#define MLEN   2048
#define DIM    128
#define NPART  296
#define NSTEPS 3125   // V/16 exactly
#define NTOK   (MLEN * BATCH * 4)   // 524288 tokens

// ---------------- scratch (device globals; no allocs allowed) ----------------
__device__ float g_w[V * BATCH];              // w[b][v] (12.8 MB)
__device__ float g_proj[V * BATCH];           // proj[v][b] (12.8 MB)
__device__ float g_u[BATCH * DIM];            // running u [b][d]
__device__ float g_part[NPART * BATCH * DIM]; // split-K partials (9.7 MB)
__device__ int   g_tok[NTOK];                 // normalized int32 tokens (2 MB)

// ---------------- mma.sync bf16 + ldmatrix (sm_80/75+ PTX) -------------------
__device__ __forceinline__ void mma_bf16(float* d, const uint32_t* a,
                                         uint32_t b0, uint32_t b1) {
    asm volatile(
        "mma.sync.aligned.m16n8k16.row.col.f32.bf16.bf16.f32 "
        "{%0,%1,%2,%3}, {%4,%5,%6,%7}, {%8,%9}, {%0,%1,%2,%3};"
        : "+f"(d[0]), "+f"(d[1]), "+f"(d[2]), "+f"(d[3])
        : "r"(a[0]), "r"(a[1]), "r"(a[2]), "r"(a[3]), "r"(b0), "r"(b1));
}
__device__ __forceinline__ void ldsm4(uint32_t* r, uint32_t a) {
    asm volatile(
        "ldmatrix.sync.aligned.m8n8.x4.shared.b16 {%0,%1,%2,%3}, [%4];"
        : "=r"(r[0]), "=r"(r[1]), "=r"(r[2]), "=r"(r[3]) : "r"(a));
}
__device__ __forceinline__ void ldsm4t(uint32_t* r, uint32_t a) {
    asm volatile(
        "ldmatrix.sync.aligned.m8n8.x4.trans.shared.b16 {%0,%1,%2,%3}, [%4];"
        : "=r"(r[0]), "=r"(r[1]), "=r"(r[2]), "=r"(r[3]) : "r"(a));
}
__device__ __forceinline__ uint32_t cvta_s(const void* p) {
    return (uint32_t)__cvta_generic_to_shared(p);
}
// packed split: (x,y) fp32 -> bf16x2 hi (x=low half), bf16x2 lo
__device__ __forceinline__ void split_pair(float x, float y, uint32_t& hi,
                                           uint32_t& lo) {
    __nv_bfloat162 h2 = __floats2bfloat162_rn(x, y);
    uint32_t h = *reinterpret_cast<uint32_t*>(&h2);
    float hx = __uint_as_float(h << 16);
    float hy = __uint_as_float(h & 0xffff0000u);
    __nv_bfloat162 l2 = __floats2bfloat162_rn(x - hx, y - hy);
    hi = h;
    lo = *reinterpret_cast<uint32_t*>(&l2);
}

// ---------------- K0: zero w + u ---------------------------------------------
__global__ void k_zero() {
    const float4 z = make_float4(0.f, 0.f, 0.f, 0.f);
    int t = blockIdx.x * blockDim.x + threadIdx.x;
    int stride = gridDim.x * blockDim.x;
    float4* w4 = reinterpret_cast<float4*>(g_w);
    for (int i = t; i < V * BATCH / 4; i += stride) w4[i] = z;
    if (t < (BATCH * DIM / 4)) reinterpret_cast<float4*>(g_u)[t] = z;
}

// ---------------- K1: convert story + hop0 count scatter (probe inline) ------
__global__ void k_prep(const int* __restrict__ s) {
    __shared__ int is32s;
    int tid = threadIdx.x;
    if (tid < 32) {
        // odd words of first 64: int64 LE -> high halves (all 0); int32 -> tokens
        int f = __any_sync(0xffffffffu, s[2 * tid + 1] != 0);
        if (tid == 0) is32s = f;
    }
    __syncthreads();
    int is32 = is32s;
    int t = blockIdx.x * blockDim.x + tid;
    if (t >= NTOK) return;
    int tok = is32 ? s[t] : s[2 * t];
    g_tok[t] = tok;
    if (tok) {
        int b = (t >> 2) & (BATCH - 1);
        atomicAdd(&g_w[b * V + tok], 1.0f);
    }
}

// ---------------- K2: proj[v][b] = C[v][:] . u[b][:]  (ldmatrix + mma) -------
#define PPS 136                       // padded k-stride (bf16), 272B rows
#define A_HI_OFF 0
#define A_LO_OFF 34816
#define B_HI_OFF 69632
#define B_LO_OFF 87040
#define PROJ_SMEM 104448

__global__ __launch_bounds__(256, 2) void k_proj_mma(const float* __restrict__ Ct) {
    extern __shared__ __align__(16) char sm[];
    int tid = threadIdx.x;
    int wid = tid >> 5, lane = tid & 31;
    int v0 = blockIdx.x * 128;

    // stage A = C[v0..+128][0..128] hi/lo, [row][k] stride PPS
#pragma unroll
    for (int i = 0; i < 16; i++) {
        int idx = tid + i * 256;          // 4096 float4s
        int row = idx >> 5, k0 = (idx & 31) * 4;
        int gv = v0 + row;
        float4 c = make_float4(0.f, 0.f, 0.f, 0.f);
        if (gv < V)
            c = *reinterpret_cast<const float4*>(Ct + (size_t)gv * DIM + k0);
        uint32_t h0, l0, h1, l1;
        split_pair(c.x, c.y, h0, l0);
        split_pair(c.z, c.w, h1, l1);
        int off = (row * PPS + k0) * 2;
        *reinterpret_cast<uint2*>(sm + A_HI_OFF + off) = make_uint2(h0, h1);
        *reinterpret_cast<uint2*>(sm + A_LO_OFF + off) = make_uint2(l0, l1);
    }
    // stage B = u[0..64][0..128]
#pragma unroll
    for (int i = 0; i < 8; i++) {
        int idx = tid + i * 256;          // 2048 float4s
        int row = idx >> 5, k0 = (idx & 31) * 4;
        float4 c = *reinterpret_cast<const float4*>(g_u + row * DIM + k0);
        uint32_t h0, l0, h1, l1;
        split_pair(c.x, c.y, h0, l0);
        split_pair(c.z, c.w, h1, l1);
        int off = (row * PPS + k0) * 2;
        *reinterpret_cast<uint2*>(sm + B_HI_OFF + off) = make_uint2(h0, h1);
        *reinterpret_cast<uint2*>(sm + B_LO_OFF + off) = make_uint2(l0, l1);
    }
    __syncthreads();

    float acc[8][4];
#pragma unroll
    for (int i = 0; i < 8; i++)
#pragma unroll
        for (int j = 0; j < 4; j++) acc[i][j] = 0.f;

    uint32_t sb = cvta_s(sm);
    int t4 = lane >> 3, r = lane & 7;
    // A lane row: m = wid*16 + (t4&1)*8 + r ; koff = (t4>>1)*8
    int rowA = wid * 16 + (t4 & 1) * 8 + r;
    int koA = (t4 >> 1) * 8;
    // B lane row (q): n = q*16 + (t4>>1)*8 + r ; koff = (t4&1)*8
    int rowB = (t4 >> 1) * 8 + r;
    int koB = (t4 & 1) * 8;

#pragma unroll
    for (int ks = 0; ks < 8; ks++) {
        int kb = ks * 16;
        uint32_t fah[4], fal[4];
        ldsm4(fah, sb + A_HI_OFF + (rowA * PPS + kb + koA) * 2);
        ldsm4(fal, sb + A_LO_OFF + (rowA * PPS + kb + koA) * 2);
        uint32_t fbh[4][4], fbl[4][4];
#pragma unroll
        for (int q = 0; q < 4; q++) {
            int boff = ((q * 16 + rowB) * PPS + kb + koB) * 2;
            ldsm4(fbh[q], sb + B_HI_OFF + boff);
            ldsm4(fbl[q], sb + B_LO_OFF + boff);
        }
#pragma unroll
        for (int q = 0; q < 4; q++)
#pragma unroll
            for (int h = 0; h < 2; h++) {
                int ng = q * 2 + h;
                mma_bf16(acc[ng], fah, fbh[q][2 * h], fbh[q][2 * h + 1]);
                mma_bf16(acc[ng], fah, fbl[q][2 * h], fbl[q][2 * h + 1]);
                mma_bf16(acc[ng], fal, fbh[q][2 * h], fbh[q][2 * h + 1]);
            }
    }
    int vA = v0 + wid * 16 + (lane >> 2), vB = vA + 8;
#pragma unroll
    for (int ng = 0; ng < 8; ng++) {
        int col = ng * 8 + 2 * (lane & 3);
        if (vA < V)
            *reinterpret_cast<float2*>(&g_proj[(size_t)vA * BATCH + col]) =
                make_float2(acc[ng][0], acc[ng][1]);
        if (vB < V)
            *reinterpret_cast<float2*>(&g_proj[(size_t)vB * BATCH + col]) =
                make_float2(acc[ng][2], acc[ng][3]);
    }
}

// ------- K3: scores + softmax + prob-scatter fused (block = b, 1024 thr) -----
__global__ __launch_bounds__(1024) void k_scores_smax_scatter() {
    __shared__ __align__(16) float sc[MLEN];
    __shared__ float red[32];
    int b = blockIdx.x, t = threadIdx.x;
    int lane = t & 31, warp = t >> 5;

    float lmax = -1e30f;
#pragma unroll
    for (int i = 0; i < 2; i++) {
        int m = i * 1024 + t;
        int4 s4 = *reinterpret_cast<const int4*>(g_tok + (m * BATCH + b) * 4);
        float s = 0.f;
        if (s4.x) s += __ldg(&g_proj[(size_t)s4.x * BATCH + b]);
        if (s4.y) s += __ldg(&g_proj[(size_t)s4.y * BATCH + b]);
        if (s4.z) s += __ldg(&g_proj[(size_t)s4.z * BATCH + b]);
        if (s4.w) s += __ldg(&g_proj[(size_t)s4.w * BATCH + b]);
        sc[m] = s;
        lmax = fmaxf(lmax, s);
    }
#pragma unroll
    for (int o = 16; o > 0; o >>= 1)
        lmax = fmaxf(lmax, __shfl_xor_sync(0xffffffffu, lmax, o));
    if (lane == 0) red[warp] = lmax;
    __syncthreads();
    if (t < 32) {
        float v = red[t];
#pragma unroll
        for (int o = 16; o > 0; o >>= 1)
            v = fmaxf(v, __shfl_xor_sync(0xffffffffu, v, o));
        if (t == 0) red[0] = v;
    }
    __syncthreads();
    float mx = red[0];
    __syncthreads();

    float lsum = 0.f;
#pragma unroll
    for (int i = 0; i < 2; i++) {
        int m = i * 1024 + t;
        float e = expf(sc[m] - mx);
        sc[m] = e;
        lsum += e;
    }
#pragma unroll
    for (int o = 16; o > 0; o >>= 1)
        lsum += __shfl_xor_sync(0xffffffffu, lsum, o);
    if (lane == 0) red[warp] = lsum;
    __syncthreads();
    if (t < 32) {
        float v = red[t];
#pragma unroll
        for (int o = 16; o > 0; o >>= 1)
            v += __shfl_xor_sync(0xffffffffu, v, o);
        if (t == 0) red[0] = v;
    }
    __syncthreads();
    float inv = 1.0f / red[0];

    float* wb = g_w + (size_t)b * V;
#pragma unroll
    for (int i = 0; i < 2; i++) {
        int m = i * 1024 + t;
        float p = sc[m] * inv;
        int4 s4 = *reinterpret_cast<const int4*>(g_tok + (m * BATCH + b) * 4);
        if (s4.x) atomicAdd(&wb[s4.x], p);
        if (s4.y) atomicAdd(&wb[s4.y], p);
        if (s4.z) atomicAdd(&wb[s4.z], p);
        if (s4.w) atomicAdd(&wb[s4.w], p);
    }
}

// ---------------- K6: o partials = w[b][v] @ C[v][d]  (ldmatrix + mma) -------
// A = w [b][j] stride 24; B = C staged [j][d] stride 136, .trans ldmatrix.
#define GPSA 24
#define CPS  136
__global__ __launch_bounds__(256, 2) void k_gemm2_mma(const float* __restrict__ Ct,
                                                      int wlo) {
    __shared__ __align__(16) __nv_bfloat16 Ah[2][64 * GPSA], Al[2][64 * GPSA];
    __shared__ __align__(16) __nv_bfloat16 Bh[2][16 * CPS], Bl[2][16 * CPS];
    int tid = threadIdx.x;
    int wid = tid >> 5, lane = tid & 31;
    int mw = wid & 1, nw = wid >> 1;          // 2 x 32 b-rows, 4 x 32 d-cols
    int s0 = (int)((long long)blockIdx.x * NSTEPS / NPART);
    int s1 = (int)((long long)(blockIdx.x + 1) * NSTEPS / NPART);

    float acc[2][4][4];
#pragma unroll
    for (int p = 0; p < 2; p++)
#pragma unroll
        for (int q = 0; q < 4; q++)
#pragma unroll
            for (int j = 0; j < 4; j++) acc[p][q][j] = 0.f;

    // staging decomposition
    int wb_ = tid >> 2, wj = (tid & 3) * 4;            // w: b row, 4 j's
    uint32_t aAh = cvta_s(&Ah[0][0]), aAl = cvta_s(&Al[0][0]);
    uint32_t aBh = cvta_s(&Bh[0][0]), aBl = cvta_s(&Bl[0][0]);
    const uint32_t ABUF = 64 * GPSA * 2, BBUF = 16 * CPS * 2;

    // fragment lane offsets
    int t4 = lane >> 3, r = lane & 7;
    uint32_t aoff[2], boff[2];
#pragma unroll
    for (int p = 0; p < 2; p++)
        aoff[p] = ((mw * 32 + p * 16 + (t4 & 1) * 8 + r) * GPSA +
                   (t4 >> 1) * 8) * 2;
#pragma unroll
    for (int q = 0; q < 2; q++)
        boff[q] = (((t4 & 1) * 8 + r) * CPS + nw * 32 + q * 16 +
                   (t4 >> 1) * 8) * 2;

    float4 pw, pc0, pc1;
    {   // prologue: load + convert + store stage 0
        int vb = s0 * 16;
        pw = *reinterpret_cast<const float4*>(&g_w[(size_t)wb_ * V + vb + wj]);
        pc0 = *reinterpret_cast<const float4*>(
            &Ct[(size_t)(vb + (tid >> 5)) * DIM + (tid & 31) * 4]);
        pc1 = *reinterpret_cast<const float4*>(
            &Ct[(size_t)(vb + 8 + (tid >> 5)) * DIM + (tid & 31) * 4]);
        uint32_t h0, l0, h1, l1;
        split_pair(pw.x, pw.y, h0, l0);
        split_pair(pw.z, pw.w, h1, l1);
        *reinterpret_cast<uint2*>(&Ah[0][wb_ * GPSA + wj]) = make_uint2(h0, h1);
        if (wlo)
            *reinterpret_cast<uint2*>(&Al[0][wb_ * GPSA + wj]) = make_uint2(l0, l1);
        int j0 = tid >> 5, d0 = (tid & 31) * 4;
        split_pair(pc0.x, pc0.y, h0, l0);
        split_pair(pc0.z, pc0.w, h1, l1);
        *reinterpret_cast<uint2*>(&Bh[0][j0 * CPS + d0]) = make_uint2(h0, h1);
        *reinterpret_cast<uint2*>(&Bl[0][j0 * CPS + d0]) = make_uint2(l0, l1);
        split_pair(pc1.x, pc1.y, h0, l0);
        split_pair(pc1.z, pc1.w, h1, l1);
        *reinterpret_cast<uint2*>(&Bh[0][(j0 + 8) * CPS + d0]) = make_uint2(h0, h1);
        *reinterpret_cast<uint2*>(&Bl[0][(j0 + 8) * CPS + d0]) = make_uint2(l0, l1);
        __syncthreads();
    }

    for (int s = s0; s < s1; s++) {
        int cur = (s - s0) & 1, nxt = cur ^ 1;
        bool more = (s + 1 < s1);
        if (more) {
            int vb = (s + 1) * 16;
            pw = *reinterpret_cast<const float4*>(&g_w[(size_t)wb_ * V + vb + wj]);
            pc0 = *reinterpret_cast<const float4*>(
                &Ct[(size_t)(vb + (tid >> 5)) * DIM + (tid & 31) * 4]);
            pc1 = *reinterpret_cast<const float4*>(
                &Ct[(size_t)(vb + 8 + (tid >> 5)) * DIM + (tid & 31) * 4]);
        }
        // fragments from buf[cur]
        uint32_t fah[2][4], fal[2][4], fbh[2][4], fbl[2][4];
        ldsm4(fah[0], aAh + cur * ABUF + aoff[0]);
        ldsm4(fah[1], aAh + cur * ABUF + aoff[1]);
        if (wlo) {
            ldsm4(fal[0], aAl + cur * ABUF + aoff[0]);
            ldsm4(fal[1], aAl + cur * ABUF + aoff[1]);
        }
        ldsm4t(fbh[0], aBh + cur * BBUF + boff[0]);
        ldsm4t(fbh[1], aBh + cur * BBUF + boff[1]);
        ldsm4t(fbl[0], aBl + cur * BBUF + boff[0]);
        ldsm4t(fbl[1], aBl + cur * BBUF + boff[1]);
#pragma unroll
        for (int p = 0; p < 2; p++)
#pragma unroll
            for (int q = 0; q < 2; q++)
#pragma unroll
                for (int h = 0; h < 2; h++) {
                    int ng = q * 2 + h;
                    mma_bf16(acc[p][ng], fah[p], fbh[q][2 * h], fbh[q][2 * h + 1]);
                    mma_bf16(acc[p][ng], fah[p], fbl[q][2 * h], fbl[q][2 * h + 1]);
                    if (wlo)
                        mma_bf16(acc[p][ng], fal[p], fbh[q][2 * h],
                                 fbh[q][2 * h + 1]);
                }
        if (more) {
            uint32_t h0, l0, h1, l1;
            split_pair(pw.x, pw.y, h0, l0);
            split_pair(pw.z, pw.w, h1, l1);
            *reinterpret_cast<uint2*>(&Ah[nxt][wb_ * GPSA + wj]) =
                make_uint2(h0, h1);
            if (wlo)
                *reinterpret_cast<uint2*>(&Al[nxt][wb_ * GPSA + wj]) =
                    make_uint2(l0, l1);
            int j0 = tid >> 5, d0 = (tid & 31) * 4;
            split_pair(pc0.x, pc0.y, h0, l0);
            split_pair(pc0.z, pc0.w, h1, l1);
            *reinterpret_cast<uint2*>(&Bh[nxt][j0 * CPS + d0]) = make_uint2(h0, h1);
            *reinterpret_cast<uint2*>(&Bl[nxt][j0 * CPS + d0]) = make_uint2(l0, l1);
            split_pair(pc1.x, pc1.y, h0, l0);
            split_pair(pc1.z, pc1.w, h1, l1);
            *reinterpret_cast<uint2*>(&Bh[nxt][(j0 + 8) * CPS + d0]) =
                make_uint2(h0, h1);
            *reinterpret_cast<uint2*>(&Bl[nxt][(j0 + 8) * CPS + d0]) =
                make_uint2(l0, l1);
        }
        __syncthreads();
    }
    float* pp = g_part + (size_t)blockIdx.x * (BATCH * DIM);
#pragma unroll
    for (int p = 0; p < 2; p++) {
        int bA = mw * 32 + p * 16 + (lane >> 2);
#pragma unroll
        for (int ng = 0; ng < 4; ng++) {
            int d = nw * 32 + ng * 8 + 2 * (lane & 3);
            *reinterpret_cast<float2*>(&pp[bA * DIM + d]) =
                make_float2(acc[p][ng][0], acc[p][ng][1]);
            *reinterpret_cast<float2*>(&pp[(bA + 8) * DIM + d]) =
                make_float2(acc[p][ng][2], acc[p][ng][3]);
        }
    }
}

// ---------------- K7: reduce partials + update u + re-zero w -----------------
__global__ void k_reduce(float scale, float* out, int zerow) {
    if (blockIdx.x < 32) {
        int i = blockIdx.x * blockDim.x + threadIdx.x;   // 8192
        float s = 0.f;
        int k = 0;
#pragma unroll
        for (; k + 8 <= NPART; k += 8) {
            float a0 = g_part[(size_t)(k + 0) * (BATCH * DIM) + i];
            float a1 = g_part[(size_t)(k + 1) * (BATCH * DIM) + i];
            float a2 = g_part[(size_t)(k + 2) * (BATCH * DIM) + i];
            float a3 = g_part[(size_t)(k + 3) * (BATCH * DIM) + i];
            float a4 = g_part[(size_t)(k + 4) * (BATCH * DIM) + i];
            float a5 = g_part[(size_t)(k + 5) * (BATCH * DIM) + i];
            float a6 = g_part[(size_t)(k + 6) * (BATCH * DIM) + i];
            float a7 = g_part[(size_t)(k + 7) * (BATCH * DIM) + i];
            s += ((a0 + a1) + (a2 + a3)) + ((a4 + a5) + (a6 + a7));
        }
        for (; k < NPART; k++) s += g_part[(size_t)k * (BATCH * DIM) + i];
        float un = g_u[i] + scale * s;
        g_u[i] = un;
        if (out) out[i] = un;
    } else if (zerow) {
        const float4 z = make_float4(0.f, 0.f, 0.f, 0.f);
        int t0 = (blockIdx.x - 32) * blockDim.x + threadIdx.x;
        int stride = (gridDim.x - 32) * blockDim.x;
        float4* w4 = reinterpret_cast<float4*>(g_w);
        for (int i = t0; i < V * BATCH / 4; i += stride) w4[i] = z;
    }
}

// -----------------------------------------------------------------------------
extern "C" void kernel_launch(void* const* d_in, const int* in_sizes, int n_in,
                              void* d_out, int out_size) {
    const void* story;
    const float* C;
    if (in_sizes[0] == NTOK) {
        story = d_in[0];
        C = (const float*)d_in[1];
    } else {
        story = d_in[1];
        C = (const float*)d_in[0];
    }
    float* out = (float*)d_out;
    const float* C1 = C + (size_t)1 * V * DIM;
    const float* C2 = C + (size_t)2 * V * DIM;
    const float* C3 = C + (size_t)3 * V * DIM;

    static int attr_set = 0;
    if (!attr_set) {
        cudaFuncSetAttribute(k_proj_mma,
                             cudaFuncAttributeMaxDynamicSharedMemorySize,
                             PROJ_SMEM);
        attr_set = 1;
    }

    const int PROJ_BLKS = (V + 127) / 128;   // 391
    const int TOK_BLKS = NTOK / 256;         // 2048

    k_zero<<<512, 256>>>();
    k_prep<<<TOK_BLKS, 256>>>((const int*)story);

    // hop 0 (counts are bf16-exact -> skip w_lo pass)
    k_gemm2_mma<<<NPART, 256>>>(C1, 0);
    k_reduce<<<512, 256>>>(1.0f / (float)MLEN, nullptr, 1);

    // hop 1
    k_proj_mma<<<PROJ_BLKS, 256, PROJ_SMEM>>>(C1);
    k_scores_smax_scatter<<<BATCH, 1024>>>();
    k_gemm2_mma<<<NPART, 256>>>(C2, 1);
    k_reduce<<<512, 256>>>(1.0f, nullptr, 1);

    // hop 2
    k_proj_mma<<<PROJ_BLKS, 256, PROJ_SMEM>>>(C2);
    k_scores_smax_scatter<<<BATCH, 1024>>>();
    k_gemm2_mma<<<NPART, 256>>>(C3, 1);
    k_reduce<<<32, 256>>>(1.0f, out, 0);
}

// round 15
// speedup vs baseline: 2.0011x; 1.0578x over previous
#include <cuda_runtime.h>
#include <cuda_bf16.h>
#include <cstdint>

#define V      50000
#define BATCH  64
#define MLEN   2048
#define DIM    128
#define NPART  296
#define NSTEPS 3125   // V/16 exactly
#define NTOK   (MLEN * BATCH * 4)   // 524288 tokens

// ---------------- scratch (device globals; no allocs allowed) ----------------
__device__ float g_w[V * BATCH];              // w[b][v] (12.8 MB)
__device__ float g_proj[V * BATCH];           // proj[v][b] (12.8 MB)
__device__ float g_u[BATCH * DIM];            // running u [b][d]
__device__ float g_part[NPART * BATCH * DIM]; // split-K partials (9.7 MB)
__device__ int   g_tok[NTOK];                 // normalized int32 tokens (2 MB)

// ---------------- mma.sync bf16 + ldmatrix (sm_80/75+ PTX) -------------------
__device__ __forceinline__ void mma_bf16(float* d, const uint32_t* a,
                                         uint32_t b0, uint32_t b1) {
    asm volatile(
        "mma.sync.aligned.m16n8k16.row.col.f32.bf16.bf16.f32 "
        "{%0,%1,%2,%3}, {%4,%5,%6,%7}, {%8,%9}, {%0,%1,%2,%3};"
        : "+f"(d[0]), "+f"(d[1]), "+f"(d[2]), "+f"(d[3])
        : "r"(a[0]), "r"(a[1]), "r"(a[2]), "r"(a[3]), "r"(b0), "r"(b1));
}
__device__ __forceinline__ void ldsm4(uint32_t* r, uint32_t a) {
    asm volatile(
        "ldmatrix.sync.aligned.m8n8.x4.shared.b16 {%0,%1,%2,%3}, [%4];"
        : "=r"(r[0]), "=r"(r[1]), "=r"(r[2]), "=r"(r[3]) : "r"(a));
}
__device__ __forceinline__ void ldsm4t(uint32_t* r, uint32_t a) {
    asm volatile(
        "ldmatrix.sync.aligned.m8n8.x4.trans.shared.b16 {%0,%1,%2,%3}, [%4];"
        : "=r"(r[0]), "=r"(r[1]), "=r"(r[2]), "=r"(r[3]) : "r"(a));
}
__device__ __forceinline__ uint32_t cvta_s(const void* p) {
    return (uint32_t)__cvta_generic_to_shared(p);
}
// packed split: (x,y) fp32 -> bf16x2 hi (x=low half), bf16x2 lo
__device__ __forceinline__ void split_pair(float x, float y, uint32_t& hi,
                                           uint32_t& lo) {
    __nv_bfloat162 h2 = __floats2bfloat162_rn(x, y);
    uint32_t h = *reinterpret_cast<uint32_t*>(&h2);
    float hx = __uint_as_float(h << 16);
    float hy = __uint_as_float(h & 0xffff0000u);
    __nv_bfloat162 l2 = __floats2bfloat162_rn(x - hx, y - hy);
    hi = h;
    lo = *reinterpret_cast<uint32_t*>(&l2);
}

// ---------------- K0: zero w + u ---------------------------------------------
__global__ void k_zero() {
    const float4 z = make_float4(0.f, 0.f, 0.f, 0.f);
    int t = blockIdx.x * blockDim.x + threadIdx.x;
    int stride = gridDim.x * blockDim.x;
    float4* w4 = reinterpret_cast<float4*>(g_w);
    for (int i = t; i < V * BATCH / 4; i += stride) w4[i] = z;
    if (t < (BATCH * DIM / 4)) reinterpret_cast<float4*>(g_u)[t] = z;
}

// ---------------- K1: convert story + hop0 count scatter (probe inline) ------
__global__ void k_prep(const int* __restrict__ s) {
    __shared__ int is32s;
    int tid = threadIdx.x;
    if (tid < 32) {
        int f = __any_sync(0xffffffffu, s[2 * tid + 1] != 0);
        if (tid == 0) is32s = f;
    }
    __syncthreads();
    int is32 = is32s;
    int t = blockIdx.x * blockDim.x + tid;
    if (t >= NTOK) return;
    int tok = is32 ? s[t] : s[2 * t];
    g_tok[t] = tok;
    if (tok) {
        int b = (t >> 2) & (BATCH - 1);
        atomicAdd(&g_w[b * V + tok], 1.0f);
    }
}

// ---------------- K2: proj[v][b] = C[v][:] . u[b][:]  (ldmatrix + mma) -------
#define PPS 136                       // padded k-stride (bf16), 272B rows
#define A_HI_OFF 0
#define A_LO_OFF 34816
#define B_HI_OFF 69632
#define B_LO_OFF 87040
#define PROJ_SMEM 104448

__global__ __launch_bounds__(256, 2) void k_proj_mma(const float* __restrict__ Ct) {
    extern __shared__ __align__(16) char sm[];
    int tid = threadIdx.x;
    int wid = tid >> 5, lane = tid & 31;
    int v0 = blockIdx.x * 128;

#pragma unroll
    for (int i = 0; i < 16; i++) {
        int idx = tid + i * 256;          // 4096 float4s
        int row = idx >> 5, k0 = (idx & 31) * 4;
        int gv = v0 + row;
        float4 c = make_float4(0.f, 0.f, 0.f, 0.f);
        if (gv < V)
            c = *reinterpret_cast<const float4*>(Ct + (size_t)gv * DIM + k0);
        uint32_t h0, l0, h1, l1;
        split_pair(c.x, c.y, h0, l0);
        split_pair(c.z, c.w, h1, l1);
        int off = (row * PPS + k0) * 2;
        *reinterpret_cast<uint2*>(sm + A_HI_OFF + off) = make_uint2(h0, h1);
        *reinterpret_cast<uint2*>(sm + A_LO_OFF + off) = make_uint2(l0, l1);
    }
#pragma unroll
    for (int i = 0; i < 8; i++) {
        int idx = tid + i * 256;          // 2048 float4s
        int row = idx >> 5, k0 = (idx & 31) * 4;
        float4 c = *reinterpret_cast<const float4*>(g_u + row * DIM + k0);
        uint32_t h0, l0, h1, l1;
        split_pair(c.x, c.y, h0, l0);
        split_pair(c.z, c.w, h1, l1);
        int off = (row * PPS + k0) * 2;
        *reinterpret_cast<uint2*>(sm + B_HI_OFF + off) = make_uint2(h0, h1);
        *reinterpret_cast<uint2*>(sm + B_LO_OFF + off) = make_uint2(l0, l1);
    }
    __syncthreads();

    float acc[8][4];
#pragma unroll
    for (int i = 0; i < 8; i++)
#pragma unroll
        for (int j = 0; j < 4; j++) acc[i][j] = 0.f;

    uint32_t sb = cvta_s(sm);
    int t4 = lane >> 3, r = lane & 7;
    int rowA = wid * 16 + (t4 & 1) * 8 + r;
    int koA = (t4 >> 1) * 8;
    int rowB = (t4 >> 1) * 8 + r;
    int koB = (t4 & 1) * 8;

#pragma unroll
    for (int ks = 0; ks < 8; ks++) {
        int kb = ks * 16;
        uint32_t fah[4], fal[4];
        ldsm4(fah, sb + A_HI_OFF + (rowA * PPS + kb + koA) * 2);
        ldsm4(fal, sb + A_LO_OFF + (rowA * PPS + kb + koA) * 2);
        uint32_t fbh[4][4], fbl[4][4];
#pragma unroll
        for (int q = 0; q < 4; q++) {
            int boff = ((q * 16 + rowB) * PPS + kb + koB) * 2;
            ldsm4(fbh[q], sb + B_HI_OFF + boff);
            ldsm4(fbl[q], sb + B_LO_OFF + boff);
        }
#pragma unroll
        for (int q = 0; q < 4; q++)
#pragma unroll
            for (int h = 0; h < 2; h++) {
                int ng = q * 2 + h;
                mma_bf16(acc[ng], fah, fbh[q][2 * h], fbh[q][2 * h + 1]);
                mma_bf16(acc[ng], fah, fbl[q][2 * h], fbl[q][2 * h + 1]);
                mma_bf16(acc[ng], fal, fbh[q][2 * h], fbh[q][2 * h + 1]);
            }
    }
    int vA = v0 + wid * 16 + (lane >> 2), vB = vA + 8;
#pragma unroll
    for (int ng = 0; ng < 8; ng++) {
        int col = ng * 8 + 2 * (lane & 3);
        if (vA < V)
            *reinterpret_cast<float2*>(&g_proj[(size_t)vA * BATCH + col]) =
                make_float2(acc[ng][0], acc[ng][1]);
        if (vB < V)
            *reinterpret_cast<float2*>(&g_proj[(size_t)vB * BATCH + col]) =
                make_float2(acc[ng][2], acc[ng][3]);
    }
}

// ------- K3: scores + softmax + prob-scatter fused (block = b, 1024 thr) -----
__global__ __launch_bounds__(1024) void k_scores_smax_scatter() {
    __shared__ __align__(16) float sc[MLEN];
    __shared__ float red[32];
    int b = blockIdx.x, t = threadIdx.x;
    int lane = t & 31, warp = t >> 5;

    float lmax = -1e30f;
#pragma unroll
    for (int i = 0; i < 2; i++) {
        int m = i * 1024 + t;
        int4 s4 = *reinterpret_cast<const int4*>(g_tok + (m * BATCH + b) * 4);
        float s = 0.f;
        if (s4.x) s += __ldg(&g_proj[(size_t)s4.x * BATCH + b]);
        if (s4.y) s += __ldg(&g_proj[(size_t)s4.y * BATCH + b]);
        if (s4.z) s += __ldg(&g_proj[(size_t)s4.z * BATCH + b]);
        if (s4.w) s += __ldg(&g_proj[(size_t)s4.w * BATCH + b]);
        sc[m] = s;
        lmax = fmaxf(lmax, s);
    }
#pragma unroll
    for (int o = 16; o > 0; o >>= 1)
        lmax = fmaxf(lmax, __shfl_xor_sync(0xffffffffu, lmax, o));
    if (lane == 0) red[warp] = lmax;
    __syncthreads();
    if (t < 32) {
        float v = red[t];
#pragma unroll
        for (int o = 16; o > 0; o >>= 1)
            v = fmaxf(v, __shfl_xor_sync(0xffffffffu, v, o));
        if (t == 0) red[0] = v;
    }
    __syncthreads();
    float mx = red[0];
    __syncthreads();

    float lsum = 0.f;
#pragma unroll
    for (int i = 0; i < 2; i++) {
        int m = i * 1024 + t;
        float e = expf(sc[m] - mx);
        sc[m] = e;
        lsum += e;
    }
#pragma unroll
    for (int o = 16; o > 0; o >>= 1)
        lsum += __shfl_xor_sync(0xffffffffu, lsum, o);
    if (lane == 0) red[warp] = lsum;
    __syncthreads();
    if (t < 32) {
        float v = red[t];
#pragma unroll
        for (int o = 16; o > 0; o >>= 1)
            v += __shfl_xor_sync(0xffffffffu, v, o);
        if (t == 0) red[0] = v;
    }
    __syncthreads();
    float inv = 1.0f / red[0];

    float* wb = g_w + (size_t)b * V;
#pragma unroll
    for (int i = 0; i < 2; i++) {
        int m = i * 1024 + t;
        float p = sc[m] * inv;
        int4 s4 = *reinterpret_cast<const int4*>(g_tok + (m * BATCH + b) * 4);
        if (s4.x) atomicAdd(&wb[s4.x], p);
        if (s4.y) atomicAdd(&wb[s4.y], p);
        if (s4.z) atomicAdd(&wb[s4.z], p);
        if (s4.w) atomicAdd(&wb[s4.w], p);
    }
}

// ---------------- K6: o partials = w[b][v] @ C[v][d]  (ldmatrix + mma) -------
#define GPSA 24
#define CPS  136
__global__ __launch_bounds__(256, 2) void k_gemm2_mma(const float* __restrict__ Ct,
                                                      int wlo) {
    __shared__ __align__(16) __nv_bfloat16 Ah[2][64 * GPSA], Al[2][64 * GPSA];
    __shared__ __align__(16) __nv_bfloat16 Bh[2][16 * CPS], Bl[2][16 * CPS];
    int tid = threadIdx.x;
    int wid = tid >> 5, lane = tid & 31;
    int mw = wid & 1, nw = wid >> 1;
    int s0 = (int)((long long)blockIdx.x * NSTEPS / NPART);
    int s1 = (int)((long long)(blockIdx.x + 1) * NSTEPS / NPART);

    float acc[2][4][4];
#pragma unroll
    for (int p = 0; p < 2; p++)
#pragma unroll
        for (int q = 0; q < 4; q++)
#pragma unroll
            for (int j = 0; j < 4; j++) acc[p][q][j] = 0.f;

    int wb_ = tid >> 2, wj = (tid & 3) * 4;
    uint32_t aAh = cvta_s(&Ah[0][0]), aAl = cvta_s(&Al[0][0]);
    uint32_t aBh = cvta_s(&Bh[0][0]), aBl = cvta_s(&Bl[0][0]);
    const uint32_t ABUF = 64 * GPSA * 2, BBUF = 16 * CPS * 2;

    int t4 = lane >> 3, r = lane & 7;
    uint32_t aoff[2], boff[2];
#pragma unroll
    for (int p = 0; p < 2; p++)
        aoff[p] = ((mw * 32 + p * 16 + (t4 & 1) * 8 + r) * GPSA +
                   (t4 >> 1) * 8) * 2;
#pragma unroll
    for (int q = 0; q < 2; q++)
        boff[q] = (((t4 & 1) * 8 + r) * CPS + nw * 32 + q * 16 +
                   (t4 >> 1) * 8) * 2;

    float4 pw, pc0, pc1;
    {
        int vb = s0 * 16;
        pw = *reinterpret_cast<const float4*>(&g_w[(size_t)wb_ * V + vb + wj]);
        pc0 = *reinterpret_cast<const float4*>(
            &Ct[(size_t)(vb + (tid >> 5)) * DIM + (tid & 31) * 4]);
        pc1 = *reinterpret_cast<const float4*>(
            &Ct[(size_t)(vb + 8 + (tid >> 5)) * DIM + (tid & 31) * 4]);
        uint32_t h0, l0, h1, l1;
        split_pair(pw.x, pw.y, h0, l0);
        split_pair(pw.z, pw.w, h1, l1);
        *reinterpret_cast<uint2*>(&Ah[0][wb_ * GPSA + wj]) = make_uint2(h0, h1);
        if (wlo)
            *reinterpret_cast<uint2*>(&Al[0][wb_ * GPSA + wj]) = make_uint2(l0, l1);
        int j0 = tid >> 5, d0 = (tid & 31) * 4;
        split_pair(pc0.x, pc0.y, h0, l0);
        split_pair(pc0.z, pc0.w, h1, l1);
        *reinterpret_cast<uint2*>(&Bh[0][j0 * CPS + d0]) = make_uint2(h0, h1);
        *reinterpret_cast<uint2*>(&Bl[0][j0 * CPS + d0]) = make_uint2(l0, l1);
        split_pair(pc1.x, pc1.y, h0, l0);
        split_pair(pc1.z, pc1.w, h1, l1);
        *reinterpret_cast<uint2*>(&Bh[0][(j0 + 8) * CPS + d0]) = make_uint2(h0, h1);
        *reinterpret_cast<uint2*>(&Bl[0][(j0 + 8) * CPS + d0]) = make_uint2(l0, l1);
        __syncthreads();
    }

    for (int s = s0; s < s1; s++) {
        int cur = (s - s0) & 1, nxt = cur ^ 1;
        bool more = (s + 1 < s1);
        if (more) {
            int vb = (s + 1) * 16;
            pw = *reinterpret_cast<const float4*>(&g_w[(size_t)wb_ * V + vb + wj]);
            pc0 = *reinterpret_cast<const float4*>(
                &Ct[(size_t)(vb + (tid >> 5)) * DIM + (tid & 31) * 4]);
            pc1 = *reinterpret_cast<const float4*>(
                &Ct[(size_t)(vb + 8 + (tid >> 5)) * DIM + (tid & 31) * 4]);
        }
        uint32_t fah[2][4], fal[2][4], fbh[2][4], fbl[2][4];
        ldsm4(fah[0], aAh + cur * ABUF + aoff[0]);
        ldsm4(fah[1], aAh + cur * ABUF + aoff[1]);
        if (wlo) {
            ldsm4(fal[0], aAl + cur * ABUF + aoff[0]);
            ldsm4(fal[1], aAl + cur * ABUF + aoff[1]);
        }
        ldsm4t(fbh[0], aBh + cur * BBUF + boff[0]);
        ldsm4t(fbh[1], aBh + cur * BBUF + boff[1]);
        ldsm4t(fbl[0], aBl + cur * BBUF + boff[0]);
        ldsm4t(fbl[1], aBl + cur * BBUF + boff[1]);
#pragma unroll
        for (int p = 0; p < 2; p++)
#pragma unroll
            for (int q = 0; q < 2; q++)
#pragma unroll
                for (int h = 0; h < 2; h++) {
                    int ng = q * 2 + h;
                    mma_bf16(acc[p][ng], fah[p], fbh[q][2 * h], fbh[q][2 * h + 1]);
                    mma_bf16(acc[p][ng], fah[p], fbl[q][2 * h], fbl[q][2 * h + 1]);
                    if (wlo)
                        mma_bf16(acc[p][ng], fal[p], fbh[q][2 * h],
                                 fbh[q][2 * h + 1]);
                }
        if (more) {
            uint32_t h0, l0, h1, l1;
            split_pair(pw.x, pw.y, h0, l0);
            split_pair(pw.z, pw.w, h1, l1);
            *reinterpret_cast<uint2*>(&Ah[nxt][wb_ * GPSA + wj]) =
                make_uint2(h0, h1);
            if (wlo)
                *reinterpret_cast<uint2*>(&Al[nxt][wb_ * GPSA + wj]) =
                    make_uint2(l0, l1);
            int j0 = tid >> 5, d0 = (tid & 31) * 4;
            split_pair(pc0.x, pc0.y, h0, l0);
            split_pair(pc0.z, pc0.w, h1, l1);
            *reinterpret_cast<uint2*>(&Bh[nxt][j0 * CPS + d0]) = make_uint2(h0, h1);
            *reinterpret_cast<uint2*>(&Bl[nxt][j0 * CPS + d0]) = make_uint2(l0, l1);
            split_pair(pc1.x, pc1.y, h0, l0);
            split_pair(pc1.z, pc1.w, h1, l1);
            *reinterpret_cast<uint2*>(&Bh[nxt][(j0 + 8) * CPS + d0]) =
                make_uint2(h0, h1);
            *reinterpret_cast<uint2*>(&Bl[nxt][(j0 + 8) * CPS + d0]) =
                make_uint2(l0, l1);
        }
        __syncthreads();
    }
    float* pp = g_part + (size_t)blockIdx.x * (BATCH * DIM);
#pragma unroll
    for (int p = 0; p < 2; p++) {
        int bA = mw * 32 + p * 16 + (lane >> 2);
#pragma unroll
        for (int ng = 0; ng < 4; ng++) {
            int d = nw * 32 + ng * 8 + 2 * (lane & 3);
            *reinterpret_cast<float2*>(&pp[bA * DIM + d]) =
                make_float2(acc[p][ng][0], acc[p][ng][1]);
            *reinterpret_cast<float2*>(&pp[(bA + 8) * DIM + d]) =
                make_float2(acc[p][ng][2], acc[p][ng][3]);
        }
    }
}

// ------- K7: parallel-k reduce + update u (+ optional out, re-zero w) --------
// Reduce part: 128 blocks x 256 thr; block covers 64 outputs x 4 k-slices (74).
#define RED_BLOCKS 128
__global__ void k_reduce(float scale, float* out, int zerow) {
    if (blockIdx.x < RED_BLOCKS) {
        __shared__ float sred[256];
        int t = threadIdx.x;
        int il = t & 63;            // output within block (coalesced across warp)
        int sl = t >> 6;            // k-slice 0..3
        int i = blockIdx.x * 64 + il;
        int k = sl * 74;
        const int k1 = k + 74;      // 4*74 = 296 = NPART exactly
        float s = 0.f;
#pragma unroll
        for (int kk = 0; kk < 9; kk++) {  // 9*8 = 72
            float a0 = g_part[(size_t)(k + 0) * (BATCH * DIM) + i];
            float a1 = g_part[(size_t)(k + 1) * (BATCH * DIM) + i];
            float a2 = g_part[(size_t)(k + 2) * (BATCH * DIM) + i];
            float a3 = g_part[(size_t)(k + 3) * (BATCH * DIM) + i];
            float a4 = g_part[(size_t)(k + 4) * (BATCH * DIM) + i];
            float a5 = g_part[(size_t)(k + 5) * (BATCH * DIM) + i];
            float a6 = g_part[(size_t)(k + 6) * (BATCH * DIM) + i];
            float a7 = g_part[(size_t)(k + 7) * (BATCH * DIM) + i];
            s += ((a0 + a1) + (a2 + a3)) + ((a4 + a5) + (a6 + a7));
            k += 8;
        }
        for (; k < k1; k++) s += g_part[(size_t)k * (BATCH * DIM) + i];
        sred[t] = s;
        __syncthreads();
        if (t < 64) {
            float v = (sred[t] + sred[t + 64]) + (sred[t + 128] + sred[t + 192]);
            int io = blockIdx.x * 64 + t;
            float un = g_u[io] + scale * v;
            g_u[io] = un;
            if (out) out[io] = un;
        }
    } else if (zerow) {
        const float4 z = make_float4(0.f, 0.f, 0.f, 0.f);
        int t0 = (blockIdx.x - RED_BLOCKS) * blockDim.x + threadIdx.x;
        int stride = (gridDim.x - RED_BLOCKS) * blockDim.x;
        float4* w4 = reinterpret_cast<float4*>(g_w);
        for (int i = t0; i < V * BATCH / 4; i += stride) w4[i] = z;
    }
}

// -----------------------------------------------------------------------------
extern "C" void kernel_launch(void* const* d_in, const int* in_sizes, int n_in,
                              void* d_out, int out_size) {
    const void* story;
    const float* C;
    if (in_sizes[0] == NTOK) {
        story = d_in[0];
        C = (const float*)d_in[1];
    } else {
        story = d_in[1];
        C = (const float*)d_in[0];
    }
    float* out = (float*)d_out;
    const float* C1 = C + (size_t)1 * V * DIM;
    const float* C2 = C + (size_t)2 * V * DIM;
    const float* C3 = C + (size_t)3 * V * DIM;

    static int attr_set = 0;
    if (!attr_set) {
        cudaFuncSetAttribute(k_proj_mma,
                             cudaFuncAttributeMaxDynamicSharedMemorySize,
                             PROJ_SMEM);
        attr_set = 1;
    }

    const int PROJ_BLKS = (V + 127) / 128;   // 391
    const int TOK_BLKS = NTOK / 256;         // 2048

    k_zero<<<512, 256>>>();
    k_prep<<<TOK_BLKS, 256>>>((const int*)story);

    // hop 0 (counts are bf16-exact -> skip w_lo pass)
    k_gemm2_mma<<<NPART, 256>>>(C1, 0);
    k_reduce<<<RED_BLOCKS + 384, 256>>>(1.0f / (float)MLEN, nullptr, 1);

    // hop 1
    k_proj_mma<<<PROJ_BLKS, 256, PROJ_SMEM>>>(C1);
    k_scores_smax_scatter<<<BATCH, 1024>>>();
    k_gemm2_mma<<<NPART, 256>>>(C2, 1);
    k_reduce<<<RED_BLOCKS + 384, 256>>>(1.0f, nullptr, 1);

    // hop 2
    k_proj_mma<<<PROJ_BLKS, 256, PROJ_SMEM>>>(C2);
    k_scores_smax_scatter<<<BATCH, 1024>>>();
    k_gemm2_mma<<<NPART, 256>>>(C3, 1);
    k_reduce<<<RED_BLOCKS, 256>>>(1.0f, out, 0);
}

// round 16
// speedup vs baseline: 2.0306x; 1.0147x over previous
#include <cuda_runtime.h>
#include <cuda_bf16.h>
#include <cstdint>

#define V      50000
#define BATCH  64
#define MLEN   2048
#define DIM    128
#define NPART  296
#define NSTEPS 3125   // V/16 exactly
#define NTOK   (MLEN * BATCH * 4)   // 524288 tokens

// ---------------- scratch (device globals; no allocs allowed) ----------------
__device__ float g_w[V * BATCH];              // w[b][v] (12.8 MB)
__device__ float g_proj[V * BATCH];           // proj[v][b] (12.8 MB)
__device__ float g_u[BATCH * DIM];            // running u [b][d]
__device__ float g_part[NPART * BATCH * DIM]; // split-K partials (9.7 MB)
__device__ int   g_tok[NTOK];                 // normalized int32 tokens (2 MB)

// ---------------- mma.sync bf16 + ldmatrix (sm_80/75+ PTX) -------------------
__device__ __forceinline__ void mma_bf16(float* d, const uint32_t* a,
                                         uint32_t b0, uint32_t b1) {
    asm volatile(
        "mma.sync.aligned.m16n8k16.row.col.f32.bf16.bf16.f32 "
        "{%0,%1,%2,%3}, {%4,%5,%6,%7}, {%8,%9}, {%0,%1,%2,%3};"
        : "+f"(d[0]), "+f"(d[1]), "+f"(d[2]), "+f"(d[3])
        : "r"(a[0]), "r"(a[1]), "r"(a[2]), "r"(a[3]), "r"(b0), "r"(b1));
}
__device__ __forceinline__ void ldsm4(uint32_t* r, uint32_t a) {
    asm volatile(
        "ldmatrix.sync.aligned.m8n8.x4.shared.b16 {%0,%1,%2,%3}, [%4];"
        : "=r"(r[0]), "=r"(r[1]), "=r"(r[2]), "=r"(r[3]) : "r"(a));
}
__device__ __forceinline__ void ldsm4t(uint32_t* r, uint32_t a) {
    asm volatile(
        "ldmatrix.sync.aligned.m8n8.x4.trans.shared.b16 {%0,%1,%2,%3}, [%4];"
        : "=r"(r[0]), "=r"(r[1]), "=r"(r[2]), "=r"(r[3]) : "r"(a));
}
__device__ __forceinline__ uint32_t cvta_s(const void* p) {
    return (uint32_t)__cvta_generic_to_shared(p);
}
// packed split: (x,y) fp32 -> bf16x2 hi (x=low half), bf16x2 lo
__device__ __forceinline__ void split_pair(float x, float y, uint32_t& hi,
                                           uint32_t& lo) {
    __nv_bfloat162 h2 = __floats2bfloat162_rn(x, y);
    uint32_t h = *reinterpret_cast<uint32_t*>(&h2);
    float hx = __uint_as_float(h << 16);
    float hy = __uint_as_float(h & 0xffff0000u);
    __nv_bfloat162 l2 = __floats2bfloat162_rn(x - hx, y - hy);
    hi = h;
    lo = *reinterpret_cast<uint32_t*>(&l2);
}

// ---------------- K0: zero w + u ---------------------------------------------
__global__ void k_zero() {
    const float4 z = make_float4(0.f, 0.f, 0.f, 0.f);
    int t = blockIdx.x * blockDim.x + threadIdx.x;
    int stride = gridDim.x * blockDim.x;
    float4* w4 = reinterpret_cast<float4*>(g_w);
    for (int i = t; i < V * BATCH / 4; i += stride) w4[i] = z;
    if (t < (BATCH * DIM / 4)) reinterpret_cast<float4*>(g_u)[t] = z;
}

// ---------------- K1: convert story + hop0 count scatter (probe inline) ------
__global__ void k_prep(const int* __restrict__ s) {
    __shared__ int is32s;
    int tid = threadIdx.x;
    if (tid < 32) {
        int f = __any_sync(0xffffffffu, s[2 * tid + 1] != 0);
        if (tid == 0) is32s = f;
    }
    __syncthreads();
    int is32 = is32s;
    int t = blockIdx.x * blockDim.x + tid;
    if (t >= NTOK) return;
    int tok = is32 ? s[t] : s[2 * t];
    g_tok[t] = tok;
    if (tok) {
        int b = (t >> 2) & (BATCH - 1);
        atomicAdd(&g_w[b * V + tok], 1.0f);
    }
}

// ---------------- K2: proj[v][b] = C[v][:] . u[b][:]  (ldmatrix + mma) -------
#define PPS 136                       // padded k-stride (bf16), 272B rows
#define A_HI_OFF 0
#define A_LO_OFF 34816
#define B_HI_OFF 69632
#define B_LO_OFF 87040
#define PROJ_SMEM 104448

__global__ __launch_bounds__(256, 2) void k_proj_mma(const float* __restrict__ Ct) {
    extern __shared__ __align__(16) char sm[];
    int tid = threadIdx.x;
    int wid = tid >> 5, lane = tid & 31;
    int v0 = blockIdx.x * 128;

#pragma unroll
    for (int i = 0; i < 16; i++) {
        int idx = tid + i * 256;          // 4096 float4s
        int row = idx >> 5, k0 = (idx & 31) * 4;
        int gv = v0 + row;
        float4 c = make_float4(0.f, 0.f, 0.f, 0.f);
        if (gv < V)
            c = *reinterpret_cast<const float4*>(Ct + (size_t)gv * DIM + k0);
        uint32_t h0, l0, h1, l1;
        split_pair(c.x, c.y, h0, l0);
        split_pair(c.z, c.w, h1, l1);
        int off = (row * PPS + k0) * 2;
        *reinterpret_cast<uint2*>(sm + A_HI_OFF + off) = make_uint2(h0, h1);
        *reinterpret_cast<uint2*>(sm + A_LO_OFF + off) = make_uint2(l0, l1);
    }
#pragma unroll
    for (int i = 0; i < 8; i++) {
        int idx = tid + i * 256;          // 2048 float4s
        int row = idx >> 5, k0 = (idx & 31) * 4;
        float4 c = *reinterpret_cast<const float4*>(g_u + row * DIM + k0);
        uint32_t h0, l0, h1, l1;
        split_pair(c.x, c.y, h0, l0);
        split_pair(c.z, c.w, h1, l1);
        int off = (row * PPS + k0) * 2;
        *reinterpret_cast<uint2*>(sm + B_HI_OFF + off) = make_uint2(h0, h1);
        *reinterpret_cast<uint2*>(sm + B_LO_OFF + off) = make_uint2(l0, l1);
    }
    __syncthreads();

    float acc[8][4];
#pragma unroll
    for (int i = 0; i < 8; i++)
#pragma unroll
        for (int j = 0; j < 4; j++) acc[i][j] = 0.f;

    uint32_t sb = cvta_s(sm);
    int t4 = lane >> 3, r = lane & 7;
    int rowA = wid * 16 + (t4 & 1) * 8 + r;
    int koA = (t4 >> 1) * 8;
    int rowB = (t4 >> 1) * 8 + r;
    int koB = (t4 & 1) * 8;

#pragma unroll
    for (int ks = 0; ks < 8; ks++) {
        int kb = ks * 16;
        uint32_t fah[4], fal[4];
        ldsm4(fah, sb + A_HI_OFF + (rowA * PPS + kb + koA) * 2);
        ldsm4(fal, sb + A_LO_OFF + (rowA * PPS + kb + koA) * 2);
        uint32_t fbh[4][4], fbl[4][4];
#pragma unroll
        for (int q = 0; q < 4; q++) {
            int boff = ((q * 16 + rowB) * PPS + kb + koB) * 2;
            ldsm4(fbh[q], sb + B_HI_OFF + boff);
            ldsm4(fbl[q], sb + B_LO_OFF + boff);
        }
#pragma unroll
        for (int q = 0; q < 4; q++)
#pragma unroll
            for (int h = 0; h < 2; h++) {
                int ng = q * 2 + h;
                mma_bf16(acc[ng], fah, fbh[q][2 * h], fbh[q][2 * h + 1]);
                mma_bf16(acc[ng], fah, fbl[q][2 * h], fbl[q][2 * h + 1]);
                mma_bf16(acc[ng], fal, fbh[q][2 * h], fbh[q][2 * h + 1]);
            }
    }
    int vA = v0 + wid * 16 + (lane >> 2), vB = vA + 8;
#pragma unroll
    for (int ng = 0; ng < 8; ng++) {
        int col = ng * 8 + 2 * (lane & 3);
        if (vA < V)
            *reinterpret_cast<float2*>(&g_proj[(size_t)vA * BATCH + col]) =
                make_float2(acc[ng][0], acc[ng][1]);
        if (vB < V)
            *reinterpret_cast<float2*>(&g_proj[(size_t)vB * BATCH + col]) =
                make_float2(acc[ng][2], acc[ng][3]);
    }
}

// -- K3: scores + softmax + zero-own-w-row + prob-scatter (block = b, 1024) ---
__global__ __launch_bounds__(1024) void k_scores_smax_scatter() {
    __shared__ __align__(16) float sc[MLEN];
    __shared__ float red[32];
    int b = blockIdx.x, t = threadIdx.x;
    int lane = t & 31, warp = t >> 5;

    float lmax = -1e30f;
#pragma unroll
    for (int i = 0; i < 2; i++) {
        int m = i * 1024 + t;
        int4 s4 = *reinterpret_cast<const int4*>(g_tok + (m * BATCH + b) * 4);
        float s = 0.f;
        if (s4.x) s += __ldg(&g_proj[(size_t)s4.x * BATCH + b]);
        if (s4.y) s += __ldg(&g_proj[(size_t)s4.y * BATCH + b]);
        if (s4.z) s += __ldg(&g_proj[(size_t)s4.z * BATCH + b]);
        if (s4.w) s += __ldg(&g_proj[(size_t)s4.w * BATCH + b]);
        sc[m] = s;
        lmax = fmaxf(lmax, s);
    }
#pragma unroll
    for (int o = 16; o > 0; o >>= 1)
        lmax = fmaxf(lmax, __shfl_xor_sync(0xffffffffu, lmax, o));
    if (lane == 0) red[warp] = lmax;
    __syncthreads();
    if (t < 32) {
        float v = red[t];
#pragma unroll
        for (int o = 16; o > 0; o >>= 1)
            v = fmaxf(v, __shfl_xor_sync(0xffffffffu, v, o));
        if (t == 0) red[0] = v;
    }
    __syncthreads();
    float mx = red[0];
    __syncthreads();

    float lsum = 0.f;
#pragma unroll
    for (int i = 0; i < 2; i++) {
        int m = i * 1024 + t;
        float e = expf(sc[m] - mx);
        sc[m] = e;
        lsum += e;
    }
#pragma unroll
    for (int o = 16; o > 0; o >>= 1)
        lsum += __shfl_xor_sync(0xffffffffu, lsum, o);
    if (lane == 0) red[warp] = lsum;
    __syncthreads();
    if (t < 32) {
        float v = red[t];
#pragma unroll
        for (int o = 16; o > 0; o >>= 1)
            v += __shfl_xor_sync(0xffffffffu, v, o);
        if (t == 0) red[0] = v;
    }
    __syncthreads();
    float inv = 1.0f / red[0];

    // zero this block's own w row (exclusive to block b), then scatter into it
    float* wb = g_w + (size_t)b * V;
    {
        const float4 z4 = make_float4(0.f, 0.f, 0.f, 0.f);
        float4* wb4 = reinterpret_cast<float4*>(wb);
        for (int i = t; i < V / 4; i += 1024) wb4[i] = z4;
    }
    __syncthreads();

#pragma unroll
    for (int i = 0; i < 2; i++) {
        int m = i * 1024 + t;
        float p = sc[m] * inv;
        int4 s4 = *reinterpret_cast<const int4*>(g_tok + (m * BATCH + b) * 4);
        if (s4.x) atomicAdd(&wb[s4.x], p);
        if (s4.y) atomicAdd(&wb[s4.y], p);
        if (s4.z) atomicAdd(&wb[s4.z], p);
        if (s4.w) atomicAdd(&wb[s4.w], p);
    }
}

// ---------------- K6: o partials = w[b][v] @ C[v][d]  (ldmatrix + mma) -------
#define GPSA 24
#define CPS  136
__global__ __launch_bounds__(256, 2) void k_gemm2_mma(const float* __restrict__ Ct,
                                                      int wlo) {
    __shared__ __align__(16) __nv_bfloat16 Ah[2][64 * GPSA], Al[2][64 * GPSA];
    __shared__ __align__(16) __nv_bfloat16 Bh[2][16 * CPS], Bl[2][16 * CPS];
    int tid = threadIdx.x;
    int wid = tid >> 5, lane = tid & 31;
    int mw = wid & 1, nw = wid >> 1;
    int s0 = (int)((long long)blockIdx.x * NSTEPS / NPART);
    int s1 = (int)((long long)(blockIdx.x + 1) * NSTEPS / NPART);

    float acc[2][4][4];
#pragma unroll
    for (int p = 0; p < 2; p++)
#pragma unroll
        for (int q = 0; q < 4; q++)
#pragma unroll
            for (int j = 0; j < 4; j++) acc[p][q][j] = 0.f;

    int wb_ = tid >> 2, wj = (tid & 3) * 4;
    uint32_t aAh = cvta_s(&Ah[0][0]), aAl = cvta_s(&Al[0][0]);
    uint32_t aBh = cvta_s(&Bh[0][0]), aBl = cvta_s(&Bl[0][0]);
    const uint32_t ABUF = 64 * GPSA * 2, BBUF = 16 * CPS * 2;

    int t4 = lane >> 3, r = lane & 7;
    uint32_t aoff[2], boff[2];
#pragma unroll
    for (int p = 0; p < 2; p++)
        aoff[p] = ((mw * 32 + p * 16 + (t4 & 1) * 8 + r) * GPSA +
                   (t4 >> 1) * 8) * 2;
#pragma unroll
    for (int q = 0; q < 2; q++)
        boff[q] = (((t4 & 1) * 8 + r) * CPS + nw * 32 + q * 16 +
                   (t4 >> 1) * 8) * 2;

    float4 pw, pc0, pc1;
    {
        int vb = s0 * 16;
        pw = *reinterpret_cast<const float4*>(&g_w[(size_t)wb_ * V + vb + wj]);
        pc0 = *reinterpret_cast<const float4*>(
            &Ct[(size_t)(vb + (tid >> 5)) * DIM + (tid & 31) * 4]);
        pc1 = *reinterpret_cast<const float4*>(
            &Ct[(size_t)(vb + 8 + (tid >> 5)) * DIM + (tid & 31) * 4]);
        uint32_t h0, l0, h1, l1;
        split_pair(pw.x, pw.y, h0, l0);
        split_pair(pw.z, pw.w, h1, l1);
        *reinterpret_cast<uint2*>(&Ah[0][wb_ * GPSA + wj]) = make_uint2(h0, h1);
        if (wlo)
            *reinterpret_cast<uint2*>(&Al[0][wb_ * GPSA + wj]) = make_uint2(l0, l1);
        int j0 = tid >> 5, d0 = (tid & 31) * 4;
        split_pair(pc0.x, pc0.y, h0, l0);
        split_pair(pc0.z, pc0.w, h1, l1);
        *reinterpret_cast<uint2*>(&Bh[0][j0 * CPS + d0]) = make_uint2(h0, h1);
        *reinterpret_cast<uint2*>(&Bl[0][j0 * CPS + d0]) = make_uint2(l0, l1);
        split_pair(pc1.x, pc1.y, h0, l0);
        split_pair(pc1.z, pc1.w, h1, l1);
        *reinterpret_cast<uint2*>(&Bh[0][(j0 + 8) * CPS + d0]) = make_uint2(h0, h1);
        *reinterpret_cast<uint2*>(&Bl[0][(j0 + 8) * CPS + d0]) = make_uint2(l0, l1);
        __syncthreads();
    }

    for (int s = s0; s < s1; s++) {
        int cur = (s - s0) & 1, nxt = cur ^ 1;
        bool more = (s + 1 < s1);
        if (more) {
            int vb = (s + 1) * 16;
            pw = *reinterpret_cast<const float4*>(&g_w[(size_t)wb_ * V + vb + wj]);
            pc0 = *reinterpret_cast<const float4*>(
                &Ct[(size_t)(vb + (tid >> 5)) * DIM + (tid & 31) * 4]);
            pc1 = *reinterpret_cast<const float4*>(
                &Ct[(size_t)(vb + 8 + (tid >> 5)) * DIM + (tid & 31) * 4]);
        }
        uint32_t fah[2][4], fal[2][4], fbh[2][4], fbl[2][4];
        ldsm4(fah[0], aAh + cur * ABUF + aoff[0]);
        ldsm4(fah[1], aAh + cur * ABUF + aoff[1]);
        if (wlo) {
            ldsm4(fal[0], aAl + cur * ABUF + aoff[0]);
            ldsm4(fal[1], aAl + cur * ABUF + aoff[1]);
        }
        ldsm4t(fbh[0], aBh + cur * BBUF + boff[0]);
        ldsm4t(fbh[1], aBh + cur * BBUF + boff[1]);
        ldsm4t(fbl[0], aBl + cur * BBUF + boff[0]);
        ldsm4t(fbl[1], aBl + cur * BBUF + boff[1]);
#pragma unroll
        for (int p = 0; p < 2; p++)
#pragma unroll
            for (int q = 0; q < 2; q++)
#pragma unroll
                for (int h = 0; h < 2; h++) {
                    int ng = q * 2 + h;
                    mma_bf16(acc[p][ng], fah[p], fbh[q][2 * h], fbh[q][2 * h + 1]);
                    mma_bf16(acc[p][ng], fah[p], fbl[q][2 * h], fbl[q][2 * h + 1]);
                    if (wlo)
                        mma_bf16(acc[p][ng], fal[p], fbh[q][2 * h],
                                 fbh[q][2 * h + 1]);
                }
        if (more) {
            uint32_t h0, l0, h1, l1;
            split_pair(pw.x, pw.y, h0, l0);
            split_pair(pw.z, pw.w, h1, l1);
            *reinterpret_cast<uint2*>(&Ah[nxt][wb_ * GPSA + wj]) =
                make_uint2(h0, h1);
            if (wlo)
                *reinterpret_cast<uint2*>(&Al[nxt][wb_ * GPSA + wj]) =
                    make_uint2(l0, l1);
            int j0 = tid >> 5, d0 = (tid & 31) * 4;
            split_pair(pc0.x, pc0.y, h0, l0);
            split_pair(pc0.z, pc0.w, h1, l1);
            *reinterpret_cast<uint2*>(&Bh[nxt][j0 * CPS + d0]) = make_uint2(h0, h1);
            *reinterpret_cast<uint2*>(&Bl[nxt][j0 * CPS + d0]) = make_uint2(l0, l1);
            split_pair(pc1.x, pc1.y, h0, l0);
            split_pair(pc1.z, pc1.w, h1, l1);
            *reinterpret_cast<uint2*>(&Bh[nxt][(j0 + 8) * CPS + d0]) =
                make_uint2(h0, h1);
            *reinterpret_cast<uint2*>(&Bl[nxt][(j0 + 8) * CPS + d0]) =
                make_uint2(l0, l1);
        }
        __syncthreads();
    }
    float* pp = g_part + (size_t)blockIdx.x * (BATCH * DIM);
#pragma unroll
    for (int p = 0; p < 2; p++) {
        int bA = mw * 32 + p * 16 + (lane >> 2);
#pragma unroll
        for (int ng = 0; ng < 4; ng++) {
            int d = nw * 32 + ng * 8 + 2 * (lane & 3);
            *reinterpret_cast<float2*>(&pp[bA * DIM + d]) =
                make_float2(acc[p][ng][0], acc[p][ng][1]);
            *reinterpret_cast<float2*>(&pp[(bA + 8) * DIM + d]) =
                make_float2(acc[p][ng][2], acc[p][ng][3]);
        }
    }
}

// ------- K7: parallel-k reduce + update u (reduce-only now) ------------------
// 256 blocks x 256 thr; block covers 32 outputs x 8 k-slices of 37.
#define RED_BLOCKS 256
__global__ void k_reduce(float scale, float* out) {
    __shared__ float sred[256];
    int t = threadIdx.x;
    int il = t & 31;                // output lane (coalesced)
    int sl = t >> 5;                // k-slice 0..7
    int i = blockIdx.x * 32 + il;
    int k = sl * 37;
    const int k1 = k + 37;          // 8*37 = 296 = NPART exactly
    float s = 0.f;
#pragma unroll
    for (int kk = 0; kk < 4; kk++) {   // 4*8 = 32
        float a0 = g_part[(size_t)(k + 0) * (BATCH * DIM) + i];
        float a1 = g_part[(size_t)(k + 1) * (BATCH * DIM) + i];
        float a2 = g_part[(size_t)(k + 2) * (BATCH * DIM) + i];
        float a3 = g_part[(size_t)(k + 3) * (BATCH * DIM) + i];
        float a4 = g_part[(size_t)(k + 4) * (BATCH * DIM) + i];
        float a5 = g_part[(size_t)(k + 5) * (BATCH * DIM) + i];
        float a6 = g_part[(size_t)(k + 6) * (BATCH * DIM) + i];
        float a7 = g_part[(size_t)(k + 7) * (BATCH * DIM) + i];
        s += ((a0 + a1) + (a2 + a3)) + ((a4 + a5) + (a6 + a7));
        k += 8;
    }
    for (; k < k1; k++) s += g_part[(size_t)k * (BATCH * DIM) + i];
    sred[t] = s;
    __syncthreads();
    if (t < 32) {
        float v = ((sred[t] + sred[t + 32]) + (sred[t + 64] + sred[t + 96])) +
                  ((sred[t + 128] + sred[t + 160]) +
                   (sred[t + 192] + sred[t + 224]));
        int io = blockIdx.x * 32 + t;
        float un = g_u[io] + scale * v;
        g_u[io] = un;
        if (out) out[io] = un;
    }
}

// -----------------------------------------------------------------------------
extern "C" void kernel_launch(void* const* d_in, const int* in_sizes, int n_in,
                              void* d_out, int out_size) {
    const void* story;
    const float* C;
    if (in_sizes[0] == NTOK) {
        story = d_in[0];
        C = (const float*)d_in[1];
    } else {
        story = d_in[1];
        C = (const float*)d_in[0];
    }
    float* out = (float*)d_out;
    const float* C1 = C + (size_t)1 * V * DIM;
    const float* C2 = C + (size_t)2 * V * DIM;
    const float* C3 = C + (size_t)3 * V * DIM;

    static int attr_set = 0;
    if (!attr_set) {
        cudaFuncSetAttribute(k_proj_mma,
                             cudaFuncAttributeMaxDynamicSharedMemorySize,
                             PROJ_SMEM);
        attr_set = 1;
    }

    const int PROJ_BLKS = (V + 127) / 128;   // 391
    const int TOK_BLKS = NTOK / 256;         // 2048

    k_zero<<<512, 256>>>();
    k_prep<<<TOK_BLKS, 256>>>((const int*)story);

    // hop 0 (counts are bf16-exact -> skip w_lo pass)
    k_gemm2_mma<<<NPART, 256>>>(C1, 0);
    k_reduce<<<RED_BLOCKS, 256>>>(1.0f / (float)MLEN, nullptr);

    // hop 1 (scores kernel zeroes its own w row before scattering)
    k_proj_mma<<<PROJ_BLKS, 256, PROJ_SMEM>>>(C1);
    k_scores_smax_scatter<<<BATCH, 1024>>>();
    k_gemm2_mma<<<NPART, 256>>>(C2, 1);
    k_reduce<<<RED_BLOCKS, 256>>>(1.0f, nullptr);

    // hop 2
    k_proj_mma<<<PROJ_BLKS, 256, PROJ_SMEM>>>(C2);
    k_scores_smax_scatter<<<BATCH, 1024>>>();
    k_gemm2_mma<<<NPART, 256>>>(C3, 1);
    k_reduce<<<RED_BLOCKS, 256>>>(1.0f, out);
}

// round 17
// speedup vs baseline: 2.0621x; 1.0155x over previous
#include <cuda_runtime.h>
#include <cuda_bf16.h>
#include <cstdint>

#define V      50000
#define BATCH  64
#define MLEN   2048
#define DIM    128
#define NPART  296
#define NSTEPS 3125   // V/16 exactly
#define NTOK   (MLEN * BATCH * 4)   // 524288 tokens

// ---------------- scratch (device globals; no allocs allowed) ----------------
__device__ float g_w[V * BATCH];              // w[b][v] (12.8 MB)
__device__ float g_proj[V * BATCH];           // proj[v][b] (12.8 MB)
__device__ float g_u[BATCH * DIM];            // running u [b][d]
__device__ float g_part[NPART * BATCH * DIM]; // split-K partials (9.7 MB)
__device__ int   g_tok[NTOK];                 // normalized int32 tokens (2 MB)

// ---------------- mma.sync bf16 + ldmatrix + cp.async ------------------------
__device__ __forceinline__ void mma_bf16(float* d, const uint32_t* a,
                                         uint32_t b0, uint32_t b1) {
    asm volatile(
        "mma.sync.aligned.m16n8k16.row.col.f32.bf16.bf16.f32 "
        "{%0,%1,%2,%3}, {%4,%5,%6,%7}, {%8,%9}, {%0,%1,%2,%3};"
        : "+f"(d[0]), "+f"(d[1]), "+f"(d[2]), "+f"(d[3])
        : "r"(a[0]), "r"(a[1]), "r"(a[2]), "r"(a[3]), "r"(b0), "r"(b1));
}
__device__ __forceinline__ void ldsm4(uint32_t* r, uint32_t a) {
    asm volatile(
        "ldmatrix.sync.aligned.m8n8.x4.shared.b16 {%0,%1,%2,%3}, [%4];"
        : "=r"(r[0]), "=r"(r[1]), "=r"(r[2]), "=r"(r[3]) : "r"(a));
}
__device__ __forceinline__ void ldsm4t(uint32_t* r, uint32_t a) {
    asm volatile(
        "ldmatrix.sync.aligned.m8n8.x4.trans.shared.b16 {%0,%1,%2,%3}, [%4];"
        : "=r"(r[0]), "=r"(r[1]), "=r"(r[2]), "=r"(r[3]) : "r"(a));
}
__device__ __forceinline__ uint32_t cvta_s(const void* p) {
    return (uint32_t)__cvta_generic_to_shared(p);
}
__device__ __forceinline__ void cp16(uint32_t smem, const void* g) {
    asm volatile("cp.async.cg.shared.global [%0], [%1], 16;"
                 :: "r"(smem), "l"(g));
}
__device__ __forceinline__ void cp_commit() {
    asm volatile("cp.async.commit_group;");
}
__device__ __forceinline__ void cp_wait1() {
    asm volatile("cp.async.wait_group 1;");
}
// packed split: (x,y) fp32 -> bf16x2 hi (x=low half), bf16x2 lo
__device__ __forceinline__ void split_pair(float x, float y, uint32_t& hi,
                                           uint32_t& lo) {
    __nv_bfloat162 h2 = __floats2bfloat162_rn(x, y);
    uint32_t h = *reinterpret_cast<uint32_t*>(&h2);
    float hx = __uint_as_float(h << 16);
    float hy = __uint_as_float(h & 0xffff0000u);
    __nv_bfloat162 l2 = __floats2bfloat162_rn(x - hx, y - hy);
    hi = h;
    lo = *reinterpret_cast<uint32_t*>(&l2);
}

// ---------------- K0: zero w + u ---------------------------------------------
__global__ void k_zero() {
    const float4 z = make_float4(0.f, 0.f, 0.f, 0.f);
    int t = blockIdx.x * blockDim.x + threadIdx.x;
    int stride = gridDim.x * blockDim.x;
    float4* w4 = reinterpret_cast<float4*>(g_w);
    for (int i = t; i < V * BATCH / 4; i += stride) w4[i] = z;
    if (t < (BATCH * DIM / 4)) reinterpret_cast<float4*>(g_u)[t] = z;
}

// ---------------- K1: convert story + hop0 count scatter (probe inline) ------
__global__ void k_prep(const int* __restrict__ s) {
    __shared__ int is32s;
    int tid = threadIdx.x;
    if (tid < 32) {
        int f = __any_sync(0xffffffffu, s[2 * tid + 1] != 0);
        if (tid == 0) is32s = f;
    }
    __syncthreads();
    int is32 = is32s;
    int t = blockIdx.x * blockDim.x + tid;
    if (t >= NTOK) return;
    int tok = is32 ? s[t] : s[2 * t];
    g_tok[t] = tok;
    if (tok) {
        int b = (t >> 2) & (BATCH - 1);
        atomicAdd(&g_w[b * V + tok], 1.0f);
    }
}

// ---------------- K2: proj[v][b] = C[v][:] . u[b][:]  (ldmatrix + mma) -------
#define PPS 136                       // padded k-stride (bf16), 272B rows
#define A_HI_OFF 0
#define A_LO_OFF 34816
#define B_HI_OFF 69632
#define B_LO_OFF 87040
#define PROJ_SMEM 104448

__global__ __launch_bounds__(256, 2) void k_proj_mma(const float* __restrict__ Ct) {
    extern __shared__ __align__(16) char sm[];
    int tid = threadIdx.x;
    int wid = tid >> 5, lane = tid & 31;
    int v0 = blockIdx.x * 128;

#pragma unroll
    for (int i = 0; i < 16; i++) {
        int idx = tid + i * 256;          // 4096 float4s
        int row = idx >> 5, k0 = (idx & 31) * 4;
        int gv = v0 + row;
        float4 c = make_float4(0.f, 0.f, 0.f, 0.f);
        if (gv < V)
            c = *reinterpret_cast<const float4*>(Ct + (size_t)gv * DIM + k0);
        uint32_t h0, l0, h1, l1;
        split_pair(c.x, c.y, h0, l0);
        split_pair(c.z, c.w, h1, l1);
        int off = (row * PPS + k0) * 2;
        *reinterpret_cast<uint2*>(sm + A_HI_OFF + off) = make_uint2(h0, h1);
        *reinterpret_cast<uint2*>(sm + A_LO_OFF + off) = make_uint2(l0, l1);
    }
#pragma unroll
    for (int i = 0; i < 8; i++) {
        int idx = tid + i * 256;          // 2048 float4s
        int row = idx >> 5, k0 = (idx & 31) * 4;
        float4 c = *reinterpret_cast<const float4*>(g_u + row * DIM + k0);
        uint32_t h0, l0, h1, l1;
        split_pair(c.x, c.y, h0, l0);
        split_pair(c.z, c.w, h1, l1);
        int off = (row * PPS + k0) * 2;
        *reinterpret_cast<uint2*>(sm + B_HI_OFF + off) = make_uint2(h0, h1);
        *reinterpret_cast<uint2*>(sm + B_LO_OFF + off) = make_uint2(l0, l1);
    }
    __syncthreads();

    float acc[8][4];
#pragma unroll
    for (int i = 0; i < 8; i++)
#pragma unroll
        for (int j = 0; j < 4; j++) acc[i][j] = 0.f;

    uint32_t sb = cvta_s(sm);
    int t4 = lane >> 3, r = lane & 7;
    int rowA = wid * 16 + (t4 & 1) * 8 + r;
    int koA = (t4 >> 1) * 8;
    int rowB = (t4 >> 1) * 8 + r;
    int koB = (t4 & 1) * 8;

#pragma unroll
    for (int ks = 0; ks < 8; ks++) {
        int kb = ks * 16;
        uint32_t fah[4], fal[4];
        ldsm4(fah, sb + A_HI_OFF + (rowA * PPS + kb + koA) * 2);
        ldsm4(fal, sb + A_LO_OFF + (rowA * PPS + kb + koA) * 2);
        uint32_t fbh[4][4], fbl[4][4];
#pragma unroll
        for (int q = 0; q < 4; q++) {
            int boff = ((q * 16 + rowB) * PPS + kb + koB) * 2;
            ldsm4(fbh[q], sb + B_HI_OFF + boff);
            ldsm4(fbl[q], sb + B_LO_OFF + boff);
        }
#pragma unroll
        for (int q = 0; q < 4; q++)
#pragma unroll
            for (int h = 0; h < 2; h++) {
                int ng = q * 2 + h;
                mma_bf16(acc[ng], fah, fbh[q][2 * h], fbh[q][2 * h + 1]);
                mma_bf16(acc[ng], fah, fbl[q][2 * h], fbl[q][2 * h + 1]);
                mma_bf16(acc[ng], fal, fbh[q][2 * h], fbh[q][2 * h + 1]);
            }
    }
    int vA = v0 + wid * 16 + (lane >> 2), vB = vA + 8;
#pragma unroll
    for (int ng = 0; ng < 8; ng++) {
        int col = ng * 8 + 2 * (lane & 3);
        if (vA < V)
            *reinterpret_cast<float2*>(&g_proj[(size_t)vA * BATCH + col]) =
                make_float2(acc[ng][0], acc[ng][1]);
        if (vB < V)
            *reinterpret_cast<float2*>(&g_proj[(size_t)vB * BATCH + col]) =
                make_float2(acc[ng][2], acc[ng][3]);
    }
}

// -- K3: scores + softmax + zero-own-w-row + prob-scatter (block = b, 1024) ---
__global__ __launch_bounds__(1024) void k_scores_smax_scatter() {
    __shared__ __align__(16) float sc[MLEN];
    __shared__ float red[32];
    int b = blockIdx.x, t = threadIdx.x;
    int lane = t & 31, warp = t >> 5;

    float lmax = -1e30f;
#pragma unroll
    for (int i = 0; i < 2; i++) {
        int m = i * 1024 + t;
        int4 s4 = *reinterpret_cast<const int4*>(g_tok + (m * BATCH + b) * 4);
        float s = 0.f;
        if (s4.x) s += __ldg(&g_proj[(size_t)s4.x * BATCH + b]);
        if (s4.y) s += __ldg(&g_proj[(size_t)s4.y * BATCH + b]);
        if (s4.z) s += __ldg(&g_proj[(size_t)s4.z * BATCH + b]);
        if (s4.w) s += __ldg(&g_proj[(size_t)s4.w * BATCH + b]);
        sc[m] = s;
        lmax = fmaxf(lmax, s);
    }
#pragma unroll
    for (int o = 16; o > 0; o >>= 1)
        lmax = fmaxf(lmax, __shfl_xor_sync(0xffffffffu, lmax, o));
    if (lane == 0) red[warp] = lmax;
    __syncthreads();
    if (t < 32) {
        float v = red[t];
#pragma unroll
        for (int o = 16; o > 0; o >>= 1)
            v = fmaxf(v, __shfl_xor_sync(0xffffffffu, v, o));
        if (t == 0) red[0] = v;
    }
    __syncthreads();
    float mx = red[0];
    __syncthreads();

    float lsum = 0.f;
#pragma unroll
    for (int i = 0; i < 2; i++) {
        int m = i * 1024 + t;
        float e = expf(sc[m] - mx);
        sc[m] = e;
        lsum += e;
    }
#pragma unroll
    for (int o = 16; o > 0; o >>= 1)
        lsum += __shfl_xor_sync(0xffffffffu, lsum, o);
    if (lane == 0) red[warp] = lsum;
    __syncthreads();
    if (t < 32) {
        float v = red[t];
#pragma unroll
        for (int o = 16; o > 0; o >>= 1)
            v += __shfl_xor_sync(0xffffffffu, v, o);
        if (t == 0) red[0] = v;
    }
    __syncthreads();
    float inv = 1.0f / red[0];

    // zero this block's own w row (exclusive to block b), then scatter into it
    float* wb = g_w + (size_t)b * V;
    {
        const float4 z4 = make_float4(0.f, 0.f, 0.f, 0.f);
        float4* wb4 = reinterpret_cast<float4*>(wb);
        for (int i = t; i < V / 4; i += 1024) wb4[i] = z4;
    }
    __syncthreads();

#pragma unroll
    for (int i = 0; i < 2; i++) {
        int m = i * 1024 + t;
        float p = sc[m] * inv;
        int4 s4 = *reinterpret_cast<const int4*>(g_tok + (m * BATCH + b) * 4);
        if (s4.x) atomicAdd(&wb[s4.x], p);
        if (s4.y) atomicAdd(&wb[s4.y], p);
        if (s4.z) atomicAdd(&wb[s4.z], p);
        if (s4.w) atomicAdd(&wb[s4.w], p);
    }
}

// ---- K6: o partials = w[b][v] @ C[v][d]  (cp.async ring + ldmatrix + mma) ---
#define GPSA 24
#define CPS  136
__global__ __launch_bounds__(256, 2) void k_gemm2_mma(const float* __restrict__ Ct,
                                                      int wlo) {
    __shared__ __align__(16) float Sw[3][1024];     // fp32 w tiles (ring)
    __shared__ __align__(16) float Sc[3][2048];     // fp32 C tiles (ring)
    __shared__ __align__(16) __nv_bfloat16 Ah[2][64 * GPSA], Al[2][64 * GPSA];
    __shared__ __align__(16) __nv_bfloat16 Bh[2][16 * CPS], Bl[2][16 * CPS];
    int tid = threadIdx.x;
    int wid = tid >> 5, lane = tid & 31;
    int mw = wid & 1, nw = wid >> 1;
    int s0 = (int)((long long)blockIdx.x * NSTEPS / NPART);
    int s1 = (int)((long long)(blockIdx.x + 1) * NSTEPS / NPART);
    int n = s1 - s0;

    float acc[2][4][4];
#pragma unroll
    for (int p = 0; p < 2; p++)
#pragma unroll
        for (int q = 0; q < 4; q++)
#pragma unroll
            for (int j = 0; j < 4; j++) acc[p][q][j] = 0.f;

    int wb_ = tid >> 2, wj = (tid & 3) * 4;   // w: b row, 4 j's
    int j0 = tid >> 5, d0 = (tid & 31) * 4;   // C: j row, 4 d's
    int t4 = lane >> 3, r = lane & 7;
    uint32_t aAh = cvta_s(&Ah[0][0]), aAl = cvta_s(&Al[0][0]);
    uint32_t aBh = cvta_s(&Bh[0][0]), aBl = cvta_s(&Bl[0][0]);
    const uint32_t ABUF = 64 * GPSA * 2, BBUF = 16 * CPS * 2;
    uint32_t aoff[2], boff[2];
#pragma unroll
    for (int p = 0; p < 2; p++)
        aoff[p] = ((mw * 32 + p * 16 + (t4 & 1) * 8 + r) * GPSA +
                   (t4 >> 1) * 8) * 2;
#pragma unroll
    for (int q = 0; q < 2; q++)
        boff[q] = (((t4 & 1) * 8 + r) * CPS + nw * 32 + q * 16 +
                   (t4 >> 1) * 8) * 2;

    uint32_t swA = cvta_s(&Sw[0][tid * 4]);
    uint32_t scA = cvta_s(&Sc[0][j0 * 128 + d0]);
    uint32_t scB = cvta_s(&Sc[0][(j0 + 8) * 128 + d0]);
    const uint32_t SWST = 1024 * 4, SCST = 2048 * 4;

    // issue stage k (ring slot st) for step s0+k
    auto issue = [&](int st, int s) {
        int vb = s * 16;
        cp16(swA + st * SWST, &g_w[(size_t)wb_ * V + vb + wj]);
        cp16(scA + st * SCST, &Ct[(size_t)(vb + j0) * DIM + d0]);
        cp16(scB + st * SCST, &Ct[(size_t)(vb + 8 + j0) * DIM + d0]);
    };
    // convert ring slot st -> bf16 buffer dst
    auto convert = [&](int st, int dst) {
        float4 w4 = *reinterpret_cast<float4*>(&Sw[st][tid * 4]);
        uint32_t h0, l0, h1, l1;
        split_pair(w4.x, w4.y, h0, l0);
        split_pair(w4.z, w4.w, h1, l1);
        *reinterpret_cast<uint2*>(&Ah[dst][wb_ * GPSA + wj]) = make_uint2(h0, h1);
        if (wlo)
            *reinterpret_cast<uint2*>(&Al[dst][wb_ * GPSA + wj]) =
                make_uint2(l0, l1);
        float4 c0 = *reinterpret_cast<float4*>(&Sc[st][j0 * 128 + d0]);
        float4 c1 = *reinterpret_cast<float4*>(&Sc[st][(j0 + 8) * 128 + d0]);
        split_pair(c0.x, c0.y, h0, l0);
        split_pair(c0.z, c0.w, h1, l1);
        *reinterpret_cast<uint2*>(&Bh[dst][j0 * CPS + d0]) = make_uint2(h0, h1);
        *reinterpret_cast<uint2*>(&Bl[dst][j0 * CPS + d0]) = make_uint2(l0, l1);
        split_pair(c1.x, c1.y, h0, l0);
        split_pair(c1.z, c1.w, h1, l1);
        *reinterpret_cast<uint2*>(&Bh[dst][(j0 + 8) * CPS + d0]) =
            make_uint2(h0, h1);
        *reinterpret_cast<uint2*>(&Bl[dst][(j0 + 8) * CPS + d0]) =
            make_uint2(l0, l1);
    };

    // prologue: issue stages 0,1; convert stage 0
    issue(0, s0);
    cp_commit();
    if (n > 1) issue(1, s0 + 1);
    cp_commit();
    cp_wait1();        // group 0 done
    convert(0, 0);
    __syncthreads();

    int st = 2;        // ring slot for next issue
    for (int k = 0; k < n; k++) {
        if (k + 2 < n) {
            issue(st, s0 + k + 2);
            if (++st == 3) st = 0;
        }
        cp_commit();   // always commit (possibly empty) to keep group numbering
        int cur = k & 1;
        // MMA from bf16[cur]
        uint32_t fah[2][4], fal[2][4], fbh[2][4], fbl[2][4];
        ldsm4(fah[0], aAh + cur * ABUF + aoff[0]);
        ldsm4(fah[1], aAh + cur * ABUF + aoff[1]);
        if (wlo) {
            ldsm4(fal[0], aAl + cur * ABUF + aoff[0]);
            ldsm4(fal[1], aAl + cur * ABUF + aoff[1]);
        }
        ldsm4t(fbh[0], aBh + cur * BBUF + boff[0]);
        ldsm4t(fbh[1], aBh + cur * BBUF + boff[1]);
        ldsm4t(fbl[0], aBl + cur * BBUF + boff[0]);
        ldsm4t(fbl[1], aBl + cur * BBUF + boff[1]);
#pragma unroll
        for (int p = 0; p < 2; p++)
#pragma unroll
            for (int q = 0; q < 2; q++)
#pragma unroll
                for (int h = 0; h < 2; h++) {
                    int ng = q * 2 + h;
                    mma_bf16(acc[p][ng], fah[p], fbh[q][2 * h], fbh[q][2 * h + 1]);
                    mma_bf16(acc[p][ng], fah[p], fbl[q][2 * h], fbl[q][2 * h + 1]);
                    if (wlo)
                        mma_bf16(acc[p][ng], fal[p], fbh[q][2 * h],
                                 fbh[q][2 * h + 1]);
                }
        if (k + 1 < n) {
            cp_wait1();                    // stage k+1 data landed
            convert((k + 1) % 3, cur ^ 1);
        }
        __syncthreads();
    }

    float* pp = g_part + (size_t)blockIdx.x * (BATCH * DIM);
#pragma unroll
    for (int p = 0; p < 2; p++) {
        int bA = mw * 32 + p * 16 + (lane >> 2);
#pragma unroll
        for (int ng = 0; ng < 4; ng++) {
            int d = nw * 32 + ng * 8 + 2 * (lane & 3);
            *reinterpret_cast<float2*>(&pp[bA * DIM + d]) =
                make_float2(acc[p][ng][0], acc[p][ng][1]);
            *reinterpret_cast<float2*>(&pp[(bA + 8) * DIM + d]) =
                make_float2(acc[p][ng][2], acc[p][ng][3]);
        }
    }
}

// ------- K7: parallel-k reduce + update u --------------------------------
// 512 blocks x 256 thr; block covers 16 outputs x 16 k-slices (~19).
#define RED_BLOCKS 512
__global__ void k_reduce(float scale, float* out) {
    __shared__ float sred[256];
    int t = threadIdx.x;
    int il = t & 15;                // output lane
    int sl = t >> 4;                // k-slice 0..15
    int i = blockIdx.x * 16 + il;
    int k = (sl * NPART) >> 4;
    int k1 = ((sl + 1) * NPART) >> 4;
    float s = 0.f;
    for (; k + 4 <= k1; k += 4) {
        float a0 = g_part[(size_t)(k + 0) * (BATCH * DIM) + i];
        float a1 = g_part[(size_t)(k + 1) * (BATCH * DIM) + i];
        float a2 = g_part[(size_t)(k + 2) * (BATCH * DIM) + i];
        float a3 = g_part[(size_t)(k + 3) * (BATCH * DIM) + i];
        s += (a0 + a1) + (a2 + a3);
    }
    for (; k < k1; k++) s += g_part[(size_t)k * (BATCH * DIM) + i];
    sred[t] = s;
    __syncthreads();
    if (t < 16) {
        float v = 0.f;
#pragma unroll
        for (int j = 0; j < 16; j++) v += sred[t + 16 * j];
        int io = blockIdx.x * 16 + t;
        float un = g_u[io] + scale * v;
        g_u[io] = un;
        if (out) out[io] = un;
    }
}

// -----------------------------------------------------------------------------
extern "C" void kernel_launch(void* const* d_in, const int* in_sizes, int n_in,
                              void* d_out, int out_size) {
    const void* story;
    const float* C;
    if (in_sizes[0] == NTOK) {
        story = d_in[0];
        C = (const float*)d_in[1];
    } else {
        story = d_in[1];
        C = (const float*)d_in[0];
    }
    float* out = (float*)d_out;
    const float* C1 = C + (size_t)1 * V * DIM;
    const float* C2 = C + (size_t)2 * V * DIM;
    const float* C3 = C + (size_t)3 * V * DIM;

    static int attr_set = 0;
    if (!attr_set) {
        cudaFuncSetAttribute(k_proj_mma,
                             cudaFuncAttributeMaxDynamicSharedMemorySize,
                             PROJ_SMEM);
        attr_set = 1;
    }

    const int PROJ_BLKS = (V + 127) / 128;   // 391
    const int TOK_BLKS = NTOK / 256;         // 2048

    k_zero<<<512, 256>>>();
    k_prep<<<TOK_BLKS, 256>>>((const int*)story);

    // hop 0 (counts are bf16-exact -> skip w_lo pass)
    k_gemm2_mma<<<NPART, 256>>>(C1, 0);
    k_reduce<<<RED_BLOCKS, 256>>>(1.0f / (float)MLEN, nullptr);

    // hop 1 (scores kernel zeroes its own w row before scattering)
    k_proj_mma<<<PROJ_BLKS, 256, PROJ_SMEM>>>(C1);
    k_scores_smax_scatter<<<BATCH, 1024>>>();
    k_gemm2_mma<<<NPART, 256>>>(C2, 1);
    k_reduce<<<RED_BLOCKS, 256>>>(1.0f, nullptr);

    // hop 2
    k_proj_mma<<<PROJ_BLKS, 256, PROJ_SMEM>>>(C2);
    k_scores_smax_scatter<<<BATCH, 1024>>>();
    k_gemm2_mma<<<NPART, 256>>>(C3, 2);
    k_reduce<<<RED_BLOCKS, 256>>>(1.0f, out);
}